// round 10
// baseline (speedup 1.0000x reference)
#include <cuda_runtime.h>
#include <math.h>

// Problem dims
#define BB 32
#define PP 100
#define NN 1000
#define DD 128
#define SPLIT 8
#define ROWS (BB*PP)           // 3200
#define RD   ((size_t)ROWS*DD) // 409600

// -------- device scratch (static, allocation-free) --------
__device__ float g_WkT [DD*DD];
__device__ float g_WvT [DD*DD];
__device__ float g_WqfT[DD*DD];
__device__ float g_WqlT[DD*DD];
__device__ float g_ek  [(size_t)BB*NN*DD];  // exp(k)
__device__ float g_ekv [(size_t)BB*NN*DD];  // exp(k)*v
__device__ float g_pnum[SPLIT*RD];          // K-split partials
__device__ float g_pden[SPLIT*RD];
__device__ float g_aft [RD];                // q, then aft (in place)

// -------- packed f32x2 helpers (sm_103a) --------
__device__ __forceinline__ void fma2(unsigned long long& d, unsigned long long a, unsigned long long b) {
    asm("fma.rn.f32x2 %0, %1, %2, %0;" : "+l"(d) : "l"(a), "l"(b));
}
__device__ __forceinline__ float2 unpk(unsigned long long v) {
    float2 r; asm("mov.b64 {%0, %1}, %2;" : "=f"(r.x), "=f"(r.y) : "l"(v)); return r;
}

// -------- kernel 1: transpose the four weight matrices --------
__global__ void transpose_w(const float* __restrict__ Wk, const float* __restrict__ Wv,
                            const float* __restrict__ Wqf, const float* __restrict__ Wql) {
    int i = blockIdx.x * 256 + threadIdx.x;     // 64*256 = 16384 = DD*DD
    int d = i >> 7, k = i & 127;
    int o = k * DD + d;
    g_WkT [o] = Wk [i];
    g_WvT [o] = Wv [i];
    g_WqfT[o] = Wqf[i];
    g_WqlT[o] = Wql[i];
}

// -------- kernel 2: k/v projection (f32x2) -> g_ek, g_ekv --------
__global__ __launch_bounds__(128) void kv_proj(const float* __restrict__ enc) {
    int d0 = blockIdx.x * 32;          // 4 d-tiles
    int r0 = blockIdx.y * 64;          // 500 row-tiles
    int tid = threadIdx.x;
    int rg = tid >> 3, cg = tid & 7;   // 16 rowgroups x 8 colgroups
    __shared__ __align__(16) float2 xs2[64][16];
    __shared__ __align__(16) float  wks[16][32];
    __shared__ __align__(16) float  wvs[16][32];
    unsigned long long aK[4][2] = {}, aV[4][2] = {};
    for (int k0 = 0; k0 < 128; k0 += 16) {
        for (int i = tid; i < 1024; i += 128) {
            int r = i >> 4, kk = i & 15;
            float v = enc[(size_t)(r0 + r) * DD + k0 + kk];
            xs2[r][kk] = make_float2(v, v);
        }
        for (int i = tid; i < 512; i += 128) {
            int kk = i >> 5, c = i & 31;
            wks[kk][c] = g_WkT[(k0 + kk) * DD + d0 + c];
            wvs[kk][c] = g_WvT[(k0 + kk) * DD + d0 + c];
        }
        __syncthreads();
#pragma unroll
        for (int kk = 0; kk < 16; kk++) {
            unsigned long long x[4];
#pragma unroll
            for (int j = 0; j < 4; j++) x[j] = *(const unsigned long long*)&xs2[rg * 4 + j][kk];
            ulonglong2 wk = *(const ulonglong2*)&wks[kk][cg * 4];
            ulonglong2 wv = *(const ulonglong2*)&wvs[kk][cg * 4];
#pragma unroll
            for (int j = 0; j < 4; j++) {
                fma2(aK[j][0], x[j], wk.x); fma2(aK[j][1], x[j], wk.y);
                fma2(aV[j][0], x[j], wv.x); fma2(aV[j][1], x[j], wv.y);
            }
        }
        __syncthreads();
    }
#pragma unroll
    for (int j = 0; j < 4; j++) {
        size_t o = (size_t)(r0 + rg * 4 + j) * DD + d0 + cg * 4;
        float2 k01 = unpk(aK[j][0]), k23 = unpk(aK[j][1]);
        float2 v01 = unpk(aV[j][0]), v23 = unpk(aV[j][1]);
        float e0 = __expf(k01.x), e1 = __expf(k01.y), e2 = __expf(k23.x), e3 = __expf(k23.y);
        *(float4*)&g_ek [o] = make_float4(e0, e1, e2, e3);
        *(float4*)&g_ekv[o] = make_float4(e0 * v01.x, e1 * v01.y, e2 * v23.x, e3 * v23.y);
    }
}

// -------- kernel 3: AFT partial num/den, fused, 8-way K-split, inline exp --------
// grid (SPLIT, 2 ptiles of 50, 32 b), 320 threads, thread = 5p x 4d x {num,den}
__global__ __launch_bounds__(320) void aft_partial(const float* __restrict__ cur_dist,
                                                   const float* __restrict__ mask,
                                                   const float* __restrict__ log_scale,
                                                   const float* __restrict__ aft_alpha) {
    int s  = blockIdx.x;               // K-split index (125 n each)
    int p0 = blockIdx.y * 50;          // p tile within batch
    int b  = blockIdx.z;
    int tid = threadIdx.x;
    int pg = tid >> 5, cg = tid & 31;  // warp = one pg (rows pg*5..+4), lanes cover d
    float c1 = log_scale[0] * aft_alpha[0];
    __shared__ __align__(16) float2 eb2[50][25];   // exp(bias), duplicated halves
    __shared__ __align__(16) float  msk[25][128];  // ek chunk
    __shared__ __align__(16) float  msv[25][128];  // ekv chunk
    unsigned long long aN[5][2] = {}, aD[5][2] = {};
    for (int c = 0; c < 5; c++) {
        int n0 = s * 125 + c * 25;
        for (int i = tid; i < 1250; i += 320) {
            int p = i / 25, nn = i - p * 25;
            size_t g = ((size_t)b * PP + p0 + p) * NN + n0 + nn;
            float e = __expf(fmaf(-c1, cur_dist[g], mask[g]));
            eb2[p][nn] = make_float2(e, e);
        }
        for (int i = tid; i < 1600; i += 320) {
            if (i < 800) {
                int nn = i >> 5, cc = i & 31;
                *(float4*)&msk[nn][cc * 4] =
                    *(const float4*)&g_ek[((size_t)b * NN + n0 + nn) * DD + cc * 4];
            } else {
                int ii = i - 800;
                int nn = ii >> 5, cc = ii & 31;
                *(float4*)&msv[nn][cc * 4] =
                    *(const float4*)&g_ekv[((size_t)b * NN + n0 + nn) * DD + cc * 4];
            }
        }
        __syncthreads();
#pragma unroll 5
        for (int nn = 0; nn < 25; nn++) {
            unsigned long long e[5];
#pragma unroll
            for (int j = 0; j < 5; j++) e[j] = *(const unsigned long long*)&eb2[pg * 5 + j][nn];
            ulonglong2 k2 = *(const ulonglong2*)&msk[nn][cg * 4];
            ulonglong2 v2 = *(const ulonglong2*)&msv[nn][cg * 4];
#pragma unroll
            for (int j = 0; j < 5; j++) {
                fma2(aN[j][0], e[j], v2.x); fma2(aN[j][1], e[j], v2.y);
                fma2(aD[j][0], e[j], k2.x); fma2(aD[j][1], e[j], k2.y);
            }
        }
        __syncthreads();
    }
#pragma unroll
    for (int j = 0; j < 5; j++) {
        int row = b * PP + p0 + pg * 5 + j;
        size_t o = (size_t)s * RD + (size_t)row * DD + cg * 4;
        float2 n01 = unpk(aN[j][0]), n23 = unpk(aN[j][1]);
        float2 d01 = unpk(aD[j][0]), d23 = unpk(aD[j][1]);
        *(float4*)&g_pnum[o] = make_float4(n01.x, n01.y, n23.x, n23.y);
        *(float4*)&g_pden[o] = make_float4(d01.x, d01.y, d23.x, d23.y);
    }
}

// -------- kernel 4: q = x1@WqfT + x2@WqlT -> g_aft (q only) --------
// 256 threads, tile 64 rows x 32 cols, thread = 2r x 4c
__global__ __launch_bounds__(256) void q_gemm(const float* __restrict__ x1, const float* __restrict__ x2) {
    int d0 = blockIdx.x * 32;          // 4 d-tiles
    int r0 = blockIdx.y * 64;          // 50 row-tiles
    int tid = threadIdx.x;
    int rg = tid >> 3, cg = tid & 7;   // 32 rowgroups x 8 colgroups
    __shared__ float x1s[64][17];
    __shared__ float x2s[64][17];
    __shared__ float wfs[16][32];
    __shared__ float wls[16][32];
    float acc[2][4] = {};
    for (int k0 = 0; k0 < 128; k0 += 16) {
        for (int i = tid; i < 1024; i += 256) {
            int r = i >> 4, kk = i & 15;
            size_t g = (size_t)(r0 + r) * DD + k0 + kk;
            x1s[r][kk] = x1[g];
            x2s[r][kk] = x2[g];
        }
        for (int i = tid; i < 512; i += 256) {
            int kk = i >> 5, c = i & 31;
            wfs[kk][c] = g_WqfT[(k0 + kk) * DD + d0 + c];
            wls[kk][c] = g_WqlT[(k0 + kk) * DD + d0 + c];
        }
        __syncthreads();
#pragma unroll
        for (int kk = 0; kk < 16; kk++) {
            float a[2], b2[2];
#pragma unroll
            for (int j = 0; j < 2; j++) { a[j] = x1s[rg * 2 + j][kk]; b2[j] = x2s[rg * 2 + j][kk]; }
            float4 wf4 = *(const float4*)&wfs[kk][cg * 4];
            float4 wl4 = *(const float4*)&wls[kk][cg * 4];
#pragma unroll
            for (int j = 0; j < 2; j++) {
                acc[j][0] += a[j] * wf4.x + b2[j] * wl4.x;
                acc[j][1] += a[j] * wf4.y + b2[j] * wl4.y;
                acc[j][2] += a[j] * wf4.z + b2[j] * wl4.z;
                acc[j][3] += a[j] * wf4.w + b2[j] * wl4.w;
            }
        }
        __syncthreads();
    }
#pragma unroll
    for (int j = 0; j < 2; j++) {
        size_t o = (size_t)(r0 + rg * 2 + j) * DD + d0 + cg * 4;
        *(float4*)&g_aft[o] = make_float4(acc[j][0], acc[j][1], acc[j][2], acc[j][3]);
    }
}

// -------- kernel 5: combine partials -> aft = sigmoid(q) * num / den (in place) --------
// pure streaming: 102400 float4 slots, grid 400 x 256
__global__ __launch_bounds__(256) void combine() {
    size_t i = (size_t)blockIdx.x * 256 + threadIdx.x;   // 0..102399
    size_t o = i * 4;
    float4 q4 = *(const float4*)&g_aft[o];
    float4 ns = make_float4(0.f, 0.f, 0.f, 0.f);
    float4 ds = make_float4(0.f, 0.f, 0.f, 0.f);
#pragma unroll
    for (int s = 0; s < SPLIT; s++) {
        float4 n4 = *(const float4*)&g_pnum[(size_t)s * RD + o];
        float4 d4 = *(const float4*)&g_pden[(size_t)s * RD + o];
        ns.x += n4.x; ns.y += n4.y; ns.z += n4.z; ns.w += n4.w;
        ds.x += d4.x; ds.y += d4.y; ds.z += d4.z; ds.w += d4.w;
    }
    float4 r;
    r.x = ns.x / ds.x / (1.0f + __expf(-q4.x));
    r.y = ns.y / ds.y / (1.0f + __expf(-q4.y));
    r.z = ns.z / ds.z / (1.0f + __expf(-q4.z));
    r.w = ns.w / ds.w / (1.0f + __expf(-q4.w));
    *(float4*)&g_aft[o] = r;
}

// -------- kernel 6: score = 10*tanh(aft@encT/sqrtD - c2*cur_dist) + mask (f32x2) --------
__global__ __launch_bounds__(200) void score_gemm(const float* __restrict__ enc,
                                                  const float* __restrict__ cur_dist,
                                                  const float* __restrict__ mask,
                                                  const float* __restrict__ log_scale,
                                                  const float* __restrict__ dist_alpha,
                                                  float* __restrict__ out) {
    int n0 = blockIdx.x * 40;
    int b  = blockIdx.y;
    int tid = threadIdx.x;
    int pg = tid / 10, cg = tid - pg * 10;    // 20 pg x 10 cg; thread = 5p x 4n
    __shared__ __align__(16) float2 afts2[100][16];
    __shared__ __align__(16) float  encs[16][44];
    unsigned long long acc[5][2] = {};
    for (int k0 = 0; k0 < 128; k0 += 16) {
        for (int i = tid; i < 1600; i += 200) {
            int p = i >> 4, kk = i & 15;
            float v = g_aft[((size_t)b * PP + p) * DD + k0 + kk];
            afts2[p][kk] = make_float2(v, v);
        }
        for (int i = tid; i < 640; i += 200) {
            int nn = i >> 4, kk = i & 15;
            encs[kk][nn] = enc[((size_t)b * NN + n0 + nn) * DD + k0 + kk];
        }
        __syncthreads();
#pragma unroll
        for (int kk = 0; kk < 16; kk++) {
            unsigned long long a[5];
#pragma unroll
            for (int j = 0; j < 5; j++) a[j] = *(const unsigned long long*)&afts2[pg * 5 + j][kk];
            ulonglong2 e2 = *(const ulonglong2*)&encs[kk][cg * 4];
#pragma unroll
            for (int j = 0; j < 5; j++) {
                fma2(acc[j][0], a[j], e2.x);
                fma2(acc[j][1], a[j], e2.y);
            }
        }
        __syncthreads();
    }
    float c2 = log_scale[0] * dist_alpha[0];
    const float inv_sqrt_d = 0.08838834764831845f;   // 1/sqrt(128)
#pragma unroll
    for (int j = 0; j < 5; j++) {
        int p = pg * 5 + j;
        size_t base = ((size_t)b * PP + p) * NN + n0 + cg * 4;
        float4 cd = *(const float4*)(cur_dist + base);
        float4 mk = *(const float4*)(mask + base);
        float2 a01 = unpk(acc[j][0]), a23 = unpk(acc[j][1]);
        float4 r;
        r.x = 10.0f * tanhf(a01.x * inv_sqrt_d - c2 * cd.x) + mk.x;
        r.y = 10.0f * tanhf(a01.y * inv_sqrt_d - c2 * cd.y) + mk.y;
        r.z = 10.0f * tanhf(a23.x * inv_sqrt_d - c2 * cd.z) + mk.z;
        r.w = 10.0f * tanhf(a23.y * inv_sqrt_d - c2 * cd.w) + mk.w;
        *(float4*)(out + base) = r;
    }
}

// -------- kernel 7: row softmax over N=1000, in place --------
__global__ __launch_bounds__(256) void softmax_rows(float* __restrict__ out) {
    size_t row = blockIdx.x;
    float* p = out + row * NN;
    int tid = threadIdx.x;
    float v[4];
    int cnt = 0;
    float mx = -3.0e38f;
    for (int i = tid; i < NN; i += 256) { v[cnt] = p[i]; mx = fmaxf(mx, v[cnt]); cnt++; }
#pragma unroll
    for (int o = 16; o; o >>= 1) mx = fmaxf(mx, __shfl_xor_sync(0xffffffffu, mx, o));
    __shared__ float sm[8], ss[8];
    int w = tid >> 5, l = tid & 31;
    if (l == 0) sm[w] = mx;
    __syncthreads();
    float m = sm[0];
#pragma unroll
    for (int i = 1; i < 8; i++) m = fmaxf(m, sm[i]);
    float s = 0.0f;
    for (int c = 0; c < cnt; c++) { v[c] = __expf(v[c] - m); s += v[c]; }
#pragma unroll
    for (int o = 16; o; o >>= 1) s += __shfl_xor_sync(0xffffffffu, s, o);
    if (l == 0) ss[w] = s;
    __syncthreads();
    float tot = 0.0f;
#pragma unroll
    for (int i = 0; i < 8; i++) tot += ss[i];
    float inv = 1.0f / tot;
    cnt = 0;
    for (int i = tid; i < NN; i += 256) { p[i] = v[cnt] * inv; cnt++; }
}

extern "C" void kernel_launch(void* const* d_in, const int* in_sizes, int n_in,
                              void* d_out, int out_size) {
    const float* enc        = (const float*)d_in[0];   // [B,N,D]
    const float* q1         = (const float*)d_in[1];   // [B,P,D]
    const float* last       = (const float*)d_in[2];   // [B,P,D]
    const float* cur_dist   = (const float*)d_in[3];   // [B,P,N]
    const float* ninf_mask  = (const float*)d_in[4];   // [B,P,N]
    const float* log_scale  = (const float*)d_in[5];   // [1]
    const float* Wq_first   = (const float*)d_in[6];   // [D,D]
    const float* Wq_last    = (const float*)d_in[7];   // [D,D]
    const float* Wk         = (const float*)d_in[8];   // [D,D]
    const float* Wv         = (const float*)d_in[9];   // [D,D]
    const float* dist_alpha = (const float*)d_in[10];  // [1]
    const float* aft_alpha  = (const float*)d_in[11];  // [1]
    float* out = (float*)d_out;                        // [B,P,N]

    transpose_w<<<64, 256>>>(Wk, Wv, Wq_first, Wq_last);
    kv_proj<<<dim3(4, 500), 128>>>(enc);
    q_gemm<<<dim3(4, 50), 256>>>(q1, last);
    aft_partial<<<dim3(SPLIT, 2, BB), 320>>>(cur_dist, ninf_mask, log_scale, aft_alpha);
    combine<<<400, 256>>>();
    score_gemm<<<dim3(25, 32), 200>>>(enc, cur_dist, ninf_mask, log_scale, dist_alpha, out);
    softmax_rows<<<3200, 256>>>(out);
}

// round 11
// speedup vs baseline: 1.1615x; 1.1615x over previous
#include <cuda_runtime.h>
#include <math.h>

// Problem dims
#define BB 32
#define PP 100
#define NN 1000
#define DD 128
#define SPLIT 8
#define ROWS (BB*PP)           // 3200
#define RD   ((size_t)ROWS*DD) // 409600

// -------- device scratch (static, allocation-free) --------
__device__ float g_WkT [DD*DD];
__device__ float g_WvT [DD*DD];
__device__ float g_WqfT[DD*DD];
__device__ float g_WqlT[DD*DD];
__device__ float g_ek  [(size_t)BB*NN*DD];  // exp(k)
__device__ float g_ekv [(size_t)BB*NN*DD];  // exp(k)*v
__device__ float g_pnum[SPLIT*RD];          // K-split partials
__device__ float g_pden[SPLIT*RD];
__device__ float g_aft [RD];                // q, then aft (in place)

// -------- packed f32x2 helpers (for score kernel) --------
__device__ __forceinline__ void fma2(unsigned long long& d, unsigned long long a, unsigned long long b) {
    asm("fma.rn.f32x2 %0, %1, %2, %0;" : "+l"(d) : "l"(a), "l"(b));
}
__device__ __forceinline__ float2 unpk(unsigned long long v) {
    float2 r; asm("mov.b64 {%0, %1}, %2;" : "=f"(r.x), "=f"(r.y) : "l"(v)); return r;
}

// -------- tf32 mma helpers --------
__device__ __forceinline__ float to_tf32(float x) {
    asm("cvt.rna.tf32.f32 %0, %1;" : "=f"(x) : "f"(x));
    return x;
}
__device__ __forceinline__ void mma_tf32(float c[4], const unsigned a[4], unsigned b0, unsigned b1) {
    asm volatile("mma.sync.aligned.m16n8k8.row.col.f32.tf32.tf32.f32 "
                 "{%0,%1,%2,%3}, {%4,%5,%6,%7}, {%8,%9}, {%0,%1,%2,%3};"
                 : "+f"(c[0]), "+f"(c[1]), "+f"(c[2]), "+f"(c[3])
                 : "r"(a[0]), "r"(a[1]), "r"(a[2]), "r"(a[3]), "r"(b0), "r"(b1));
}

// -------- kernel 1: transpose the four weight matrices --------
__global__ void transpose_w(const float* __restrict__ Wk, const float* __restrict__ Wv,
                            const float* __restrict__ Wqf, const float* __restrict__ Wql) {
    int i = blockIdx.x * 256 + threadIdx.x;     // 64*256 = 16384 = DD*DD
    int d = i >> 7, k = i & 127;
    int o = k * DD + d;
    g_WkT [o] = Wk [i];
    g_WvT [o] = Wv [i];
    g_WqfT[o] = Wqf[i];
    g_WqlT[o] = Wql[i];
}

// -------- kernel 2: k/v projection via tf32 MMA --------
// per CTA: 64 rows x (128 d for K and V), K=128. 8 warps as 2(m) x 4(n).
__global__ __launch_bounds__(256) void kv_mma(const float* __restrict__ enc) {
    int r0 = blockIdx.x * 64;          // 500 row tiles
    int tid = threadIdx.x, lane = tid & 31, wid = tid >> 5;
    int wm = wid >> 2, wn = wid & 3;   // 2 x 4 warps
    int g = lane >> 2, tg = lane & 3;
    __shared__ float As[64][18];
    __shared__ float Bk[16][136];
    __shared__ float Bv[16][136];
    float accK[2][4][4] = {}, accV[2][4][4] = {};
    for (int c = 0; c < 8; c++) {
        int kb = c * 16;
        for (int i = tid; i < 1024; i += 256) {
            int p = i >> 4, kk = i & 15;
            As[p][kk] = to_tf32(enc[(size_t)(r0 + p) * DD + kb + kk]);
        }
        for (int i = tid; i < 2048; i += 256) {
            int kk = i >> 7, d = i & 127;
            Bk[kk][d] = to_tf32(g_WkT[(kb + kk) * DD + d]);
            Bv[kk][d] = to_tf32(g_WvT[(kb + kk) * DD + d]);
        }
        __syncthreads();
#pragma unroll
        for (int k8 = 0; k8 < 16; k8 += 8) {
            unsigned a[2][4];
#pragma unroll
            for (int mt = 0; mt < 2; mt++) {
                int r = wm * 32 + mt * 16 + g;
                a[mt][0] = __float_as_uint(As[r    ][k8 + tg    ]);
                a[mt][1] = __float_as_uint(As[r + 8][k8 + tg    ]);
                a[mt][2] = __float_as_uint(As[r    ][k8 + tg + 4]);
                a[mt][3] = __float_as_uint(As[r + 8][k8 + tg + 4]);
            }
#pragma unroll
            for (int nt = 0; nt < 4; nt++) {
                int d = wn * 32 + nt * 8 + g;
                unsigned bk0 = __float_as_uint(Bk[k8 + tg    ][d]);
                unsigned bk1 = __float_as_uint(Bk[k8 + tg + 4][d]);
                unsigned bv0 = __float_as_uint(Bv[k8 + tg    ][d]);
                unsigned bv1 = __float_as_uint(Bv[k8 + tg + 4][d]);
#pragma unroll
                for (int mt = 0; mt < 2; mt++) {
                    mma_tf32(accK[mt][nt], a[mt], bk0, bk1);
                    mma_tf32(accV[mt][nt], a[mt], bv0, bv1);
                }
            }
        }
        __syncthreads();
    }
#pragma unroll
    for (int mt = 0; mt < 2; mt++) {
        int r = wm * 32 + mt * 16 + g;
#pragma unroll
        for (int nt = 0; nt < 4; nt++) {
            int d = wn * 32 + nt * 8 + tg * 2;
            size_t o0 = (size_t)(r0 + r) * DD + d;
            size_t o1 = (size_t)(r0 + r + 8) * DD + d;
            float e0 = __expf(accK[mt][nt][0]), e1 = __expf(accK[mt][nt][1]);
            float e2 = __expf(accK[mt][nt][2]), e3 = __expf(accK[mt][nt][3]);
            *(float2*)&g_ek [o0] = make_float2(e0, e1);
            *(float2*)&g_ekv[o0] = make_float2(e0 * accV[mt][nt][0], e1 * accV[mt][nt][1]);
            *(float2*)&g_ek [o1] = make_float2(e2, e3);
            *(float2*)&g_ekv[o1] = make_float2(e2 * accV[mt][nt][2], e3 * accV[mt][nt][3]);
        }
    }
}

// -------- kernel 3: AFT num/den via tf32 MMA, 8-way K-split, inline exp --------
// grid (SPLIT, 2 p-halves of 50, 32 b). per CTA: M=64 (50 p) x N=128 d x {num,den}, K=125 pad 128.
__global__ __launch_bounds__(256) void aft_mma(const float* __restrict__ cur_dist,
                                               const float* __restrict__ mask,
                                               const float* __restrict__ log_scale,
                                               const float* __restrict__ aft_alpha) {
    int s = blockIdx.x, ph = blockIdx.y, b = blockIdx.z;
    int tid = threadIdx.x, lane = tid & 31, wid = tid >> 5;
    int wm = wid >> 2, wn = wid & 3;   // 2 x 4 warps
    int g = lane >> 2, tg = lane & 3;
    float c1 = log_scale[0] * aft_alpha[0];
    __shared__ float As[64][18];
    __shared__ float Bv[16][136];
    __shared__ float Bk[16][136];
    float accN[2][4][4] = {}, accD[2][4][4] = {};
    int kbase0 = s * 125;
    for (int c = 0; c < 8; c++) {
        int kb = c * 16;
        for (int i = tid; i < 1024; i += 256) {
            int p = i >> 4, kk = i & 15;
            float e = 0.f;
            if (p < 50 && kb + kk < 125) {
                size_t gi = ((size_t)b * PP + ph * 50 + p) * NN + kbase0 + kb + kk;
                e = __expf(fmaf(-c1, cur_dist[gi], mask[gi]));
            }
            As[p][kk] = to_tf32(e);
        }
        for (int i = tid; i < 2048; i += 256) {
            int kk = i >> 7, d = i & 127;
            float vk = 0.f, vv = 0.f;
            if (kb + kk < 125) {
                size_t gi = ((size_t)b * NN + kbase0 + kb + kk) * DD + d;
                vk = g_ek[gi]; vv = g_ekv[gi];
            }
            Bk[kk][d] = to_tf32(vk);
            Bv[kk][d] = to_tf32(vv);
        }
        __syncthreads();
#pragma unroll
        for (int k8 = 0; k8 < 16; k8 += 8) {
            unsigned a[2][4];
#pragma unroll
            for (int mt = 0; mt < 2; mt++) {
                int r = wm * 32 + mt * 16 + g;
                a[mt][0] = __float_as_uint(As[r    ][k8 + tg    ]);
                a[mt][1] = __float_as_uint(As[r + 8][k8 + tg    ]);
                a[mt][2] = __float_as_uint(As[r    ][k8 + tg + 4]);
                a[mt][3] = __float_as_uint(As[r + 8][k8 + tg + 4]);
            }
#pragma unroll
            for (int nt = 0; nt < 4; nt++) {
                int d = wn * 32 + nt * 8 + g;
                unsigned bv0 = __float_as_uint(Bv[k8 + tg    ][d]);
                unsigned bv1 = __float_as_uint(Bv[k8 + tg + 4][d]);
                unsigned bk0 = __float_as_uint(Bk[k8 + tg    ][d]);
                unsigned bk1 = __float_as_uint(Bk[k8 + tg + 4][d]);
#pragma unroll
                for (int mt = 0; mt < 2; mt++) {
                    mma_tf32(accN[mt][nt], a[mt], bv0, bv1);
                    mma_tf32(accD[mt][nt], a[mt], bk0, bk1);
                }
            }
        }
        __syncthreads();
    }
#pragma unroll
    for (int mt = 0; mt < 2; mt++) {
        int r = wm * 32 + mt * 16 + g;     // local p (c0,c1); r+8 for (c2,c3)
#pragma unroll
        for (int nt = 0; nt < 4; nt++) {
            int d = wn * 32 + nt * 8 + tg * 2;
            if (r < 50) {
                size_t o = (size_t)s * RD + ((size_t)b * PP + ph * 50 + r) * DD + d;
                *(float2*)&g_pnum[o] = make_float2(accN[mt][nt][0], accN[mt][nt][1]);
                *(float2*)&g_pden[o] = make_float2(accD[mt][nt][0], accD[mt][nt][1]);
            }
            if (r + 8 < 50) {
                size_t o = (size_t)s * RD + ((size_t)b * PP + ph * 50 + r + 8) * DD + d;
                *(float2*)&g_pnum[o] = make_float2(accN[mt][nt][2], accN[mt][nt][3]);
                *(float2*)&g_pden[o] = make_float2(accD[mt][nt][2], accD[mt][nt][3]);
            }
        }
    }
}

// -------- kernel 4: q = x1@WqfT + x2@WqlT -> g_aft (q only) --------
__global__ __launch_bounds__(256) void q_gemm(const float* __restrict__ x1, const float* __restrict__ x2) {
    int d0 = blockIdx.x * 32;          // 4 d-tiles
    int r0 = blockIdx.y * 64;          // 50 row-tiles
    int tid = threadIdx.x;
    int rg = tid >> 3, cg = tid & 7;   // 32 rowgroups x 8 colgroups
    __shared__ float x1s[64][17];
    __shared__ float x2s[64][17];
    __shared__ float wfs[16][32];
    __shared__ float wls[16][32];
    float acc[2][4] = {};
    for (int k0 = 0; k0 < 128; k0 += 16) {
        for (int i = tid; i < 1024; i += 256) {
            int r = i >> 4, kk = i & 15;
            size_t g = (size_t)(r0 + r) * DD + k0 + kk;
            x1s[r][kk] = x1[g];
            x2s[r][kk] = x2[g];
        }
        for (int i = tid; i < 512; i += 256) {
            int kk = i >> 5, c = i & 31;
            wfs[kk][c] = g_WqfT[(k0 + kk) * DD + d0 + c];
            wls[kk][c] = g_WqlT[(k0 + kk) * DD + d0 + c];
        }
        __syncthreads();
#pragma unroll
        for (int kk = 0; kk < 16; kk++) {
            float a[2], b2[2];
#pragma unroll
            for (int j = 0; j < 2; j++) { a[j] = x1s[rg * 2 + j][kk]; b2[j] = x2s[rg * 2 + j][kk]; }
            float4 wf4 = *(const float4*)&wfs[kk][cg * 4];
            float4 wl4 = *(const float4*)&wls[kk][cg * 4];
#pragma unroll
            for (int j = 0; j < 2; j++) {
                acc[j][0] += a[j] * wf4.x + b2[j] * wl4.x;
                acc[j][1] += a[j] * wf4.y + b2[j] * wl4.y;
                acc[j][2] += a[j] * wf4.z + b2[j] * wl4.z;
                acc[j][3] += a[j] * wf4.w + b2[j] * wl4.w;
            }
        }
        __syncthreads();
    }
#pragma unroll
    for (int j = 0; j < 2; j++) {
        size_t o = (size_t)(r0 + rg * 2 + j) * DD + d0 + cg * 4;
        *(float4*)&g_aft[o] = make_float4(acc[j][0], acc[j][1], acc[j][2], acc[j][3]);
    }
}

// -------- kernel 5: combine partials -> aft = sigmoid(q) * num / den (in place) --------
__global__ __launch_bounds__(256) void combine() {
    size_t i = (size_t)blockIdx.x * 256 + threadIdx.x;   // 0..102399
    size_t o = i * 4;
    float4 q4 = *(const float4*)&g_aft[o];
    float4 ns = make_float4(0.f, 0.f, 0.f, 0.f);
    float4 ds = make_float4(0.f, 0.f, 0.f, 0.f);
#pragma unroll
    for (int s = 0; s < SPLIT; s++) {
        float4 n4 = *(const float4*)&g_pnum[(size_t)s * RD + o];
        float4 d4 = *(const float4*)&g_pden[(size_t)s * RD + o];
        ns.x += n4.x; ns.y += n4.y; ns.z += n4.z; ns.w += n4.w;
        ds.x += d4.x; ds.y += d4.y; ds.z += d4.z; ds.w += d4.w;
    }
    float4 r;
    r.x = ns.x / ds.x / (1.0f + __expf(-q4.x));
    r.y = ns.y / ds.y / (1.0f + __expf(-q4.y));
    r.z = ns.z / ds.z / (1.0f + __expf(-q4.z));
    r.w = ns.w / ds.w / (1.0f + __expf(-q4.w));
    *(float4*)&g_aft[o] = r;
}

// -------- kernel 6: score = 10*tanh(aft@encT/sqrtD - c2*cur_dist) + mask (f32x2) --------
__global__ __launch_bounds__(200) void score_gemm(const float* __restrict__ enc,
                                                  const float* __restrict__ cur_dist,
                                                  const float* __restrict__ mask,
                                                  const float* __restrict__ log_scale,
                                                  const float* __restrict__ dist_alpha,
                                                  float* __restrict__ out) {
    int n0 = blockIdx.x * 40;
    int b  = blockIdx.y;
    int tid = threadIdx.x;
    int pg = tid / 10, cg = tid - pg * 10;    // 20 pg x 10 cg; thread = 5p x 4n
    __shared__ __align__(16) float2 afts2[100][16];
    __shared__ __align__(16) float  encs[16][44];
    unsigned long long acc[5][2] = {};
    for (int k0 = 0; k0 < 128; k0 += 16) {
        for (int i = tid; i < 1600; i += 200) {
            int p = i >> 4, kk = i & 15;
            float v = g_aft[((size_t)b * PP + p) * DD + k0 + kk];
            afts2[p][kk] = make_float2(v, v);
        }
        for (int i = tid; i < 640; i += 200) {
            int nn = i >> 4, kk = i & 15;
            encs[kk][nn] = enc[((size_t)b * NN + n0 + nn) * DD + k0 + kk];
        }
        __syncthreads();
#pragma unroll
        for (int kk = 0; kk < 16; kk++) {
            unsigned long long a[5];
#pragma unroll
            for (int j = 0; j < 5; j++) a[j] = *(const unsigned long long*)&afts2[pg * 5 + j][kk];
            ulonglong2 e2 = *(const ulonglong2*)&encs[kk][cg * 4];
#pragma unroll
            for (int j = 0; j < 5; j++) {
                fma2(acc[j][0], a[j], e2.x);
                fma2(acc[j][1], a[j], e2.y);
            }
        }
        __syncthreads();
    }
    float c2 = log_scale[0] * dist_alpha[0];
    const float inv_sqrt_d = 0.08838834764831845f;   // 1/sqrt(128)
#pragma unroll
    for (int j = 0; j < 5; j++) {
        int p = pg * 5 + j;
        size_t base = ((size_t)b * PP + p) * NN + n0 + cg * 4;
        float4 cd = *(const float4*)(cur_dist + base);
        float4 mk = *(const float4*)(mask + base);
        float2 a01 = unpk(acc[j][0]), a23 = unpk(acc[j][1]);
        float4 r;
        r.x = 10.0f * tanhf(a01.x * inv_sqrt_d - c2 * cd.x) + mk.x;
        r.y = 10.0f * tanhf(a01.y * inv_sqrt_d - c2 * cd.y) + mk.y;
        r.z = 10.0f * tanhf(a23.x * inv_sqrt_d - c2 * cd.z) + mk.z;
        r.w = 10.0f * tanhf(a23.y * inv_sqrt_d - c2 * cd.w) + mk.w;
        *(float4*)(out + base) = r;
    }
}

// -------- kernel 7: row softmax over N=1000, in place --------
__global__ __launch_bounds__(256) void softmax_rows(float* __restrict__ out) {
    size_t row = blockIdx.x;
    float* p = out + row * NN;
    int tid = threadIdx.x;
    float v[4];
    int cnt = 0;
    float mx = -3.0e38f;
    for (int i = tid; i < NN; i += 256) { v[cnt] = p[i]; mx = fmaxf(mx, v[cnt]); cnt++; }
#pragma unroll
    for (int o = 16; o; o >>= 1) mx = fmaxf(mx, __shfl_xor_sync(0xffffffffu, mx, o));
    __shared__ float sm[8], ss[8];
    int w = tid >> 5, l = tid & 31;
    if (l == 0) sm[w] = mx;
    __syncthreads();
    float m = sm[0];
#pragma unroll
    for (int i = 1; i < 8; i++) m = fmaxf(m, sm[i]);
    float s = 0.0f;
    for (int c = 0; c < cnt; c++) { v[c] = __expf(v[c] - m); s += v[c]; }
#pragma unroll
    for (int o = 16; o; o >>= 1) s += __shfl_xor_sync(0xffffffffu, s, o);
    if (l == 0) ss[w] = s;
    __syncthreads();
    float tot = 0.0f;
#pragma unroll
    for (int i = 0; i < 8; i++) tot += ss[i];
    float inv = 1.0f / tot;
    cnt = 0;
    for (int i = tid; i < NN; i += 256) { p[i] = v[cnt] * inv; cnt++; }
}

extern "C" void kernel_launch(void* const* d_in, const int* in_sizes, int n_in,
                              void* d_out, int out_size) {
    const float* enc        = (const float*)d_in[0];   // [B,N,D]
    const float* q1         = (const float*)d_in[1];   // [B,P,D]
    const float* last       = (const float*)d_in[2];   // [B,P,D]
    const float* cur_dist   = (const float*)d_in[3];   // [B,P,N]
    const float* ninf_mask  = (const float*)d_in[4];   // [B,P,N]
    const float* log_scale  = (const float*)d_in[5];   // [1]
    const float* Wq_first   = (const float*)d_in[6];   // [D,D]
    const float* Wq_last    = (const float*)d_in[7];   // [D,D]
    const float* Wk         = (const float*)d_in[8];   // [D,D]
    const float* Wv         = (const float*)d_in[9];   // [D,D]
    const float* dist_alpha = (const float*)d_in[10];  // [1]
    const float* aft_alpha  = (const float*)d_in[11];  // [1]
    float* out = (float*)d_out;                        // [B,P,N]

    transpose_w<<<64, 256>>>(Wk, Wv, Wq_first, Wq_last);
    kv_mma<<<500, 256>>>(enc);
    q_gemm<<<dim3(4, 50), 256>>>(q1, last);
    aft_mma<<<dim3(SPLIT, 2, BB), 256>>>(cur_dist, ninf_mask, log_scale, aft_alpha);
    combine<<<400, 256>>>();
    score_gemm<<<dim3(25, 32), 200>>>(enc, cur_dist, ninf_mask, log_scale, dist_alpha, out);
    softmax_rows<<<3200, 256>>>(out);
}

// round 12
// speedup vs baseline: 1.4856x; 1.2791x over previous
#include <cuda_runtime.h>
#include <math.h>

// Problem dims
#define BB 32
#define PP 100
#define NN 1000
#define DD 128
#define SPLIT 8
#define ROWS (BB*PP)           // 3200
#define RD   ((size_t)ROWS*DD) // 409600
#define NPAD (SPLIT*128)       // 1024 padded n per batch

// -------- device scratch (static, allocation-free) --------
__device__ float g_WkT [DD*DD];   // tf32-rounded
__device__ float g_WvT [DD*DD];   // tf32-rounded
__device__ float g_WqfT[DD*DD];
__device__ float g_WqlT[DD*DD];
__device__ float g_ekp [(size_t)BB*NPAD*DD];  // exp(k), tf32, padded (pads stay 0)
__device__ float g_ekvp[(size_t)BB*NPAD*DD];  // exp(k)*v, tf32, padded
__device__ float g_pnum[SPLIT*RD];            // K-split partials
__device__ float g_pden[SPLIT*RD];
__device__ float g_aft [RD];                  // q, then aft (in place)

// -------- packed f32x2 helpers (for score kernel) --------
__device__ __forceinline__ void fma2(unsigned long long& d, unsigned long long a, unsigned long long b) {
    asm("fma.rn.f32x2 %0, %1, %2, %0;" : "+l"(d) : "l"(a), "l"(b));
}
__device__ __forceinline__ float2 unpk(unsigned long long v) {
    float2 r; asm("mov.b64 {%0, %1}, %2;" : "=f"(r.x), "=f"(r.y) : "l"(v)); return r;
}

// -------- tf32 mma helpers --------
__device__ __forceinline__ float to_tf32(float x) {
    asm("cvt.rna.tf32.f32 %0, %1;" : "=f"(x) : "f"(x));
    return x;
}
__device__ __forceinline__ void mma_tf32(float c[4], const unsigned a[4], unsigned b0, unsigned b1) {
    asm volatile("mma.sync.aligned.m16n8k8.row.col.f32.tf32.tf32.f32 "
                 "{%0,%1,%2,%3}, {%4,%5,%6,%7}, {%8,%9}, {%0,%1,%2,%3};"
                 : "+f"(c[0]), "+f"(c[1]), "+f"(c[2]), "+f"(c[3])
                 : "r"(a[0]), "r"(a[1]), "r"(a[2]), "r"(a[3]), "r"(b0), "r"(b1));
}

// -------- cp.async helpers --------
__device__ __forceinline__ void cpa16(void* dst_smem, const float* src) {
    unsigned s = (unsigned)__cvta_generic_to_shared(dst_smem);
    asm volatile("cp.async.cg.shared.global [%0], [%1], 16;\n" :: "r"(s), "l"(src));
}
#define CP_COMMIT() asm volatile("cp.async.commit_group;\n" ::: "memory")
#define CP_WAIT0()  asm volatile("cp.async.wait_group 0;\n" ::: "memory")

// -------- kernel 1: transpose weights (Wk/Wv pre-rounded to tf32) --------
__global__ void transpose_w(const float* __restrict__ Wk, const float* __restrict__ Wv,
                            const float* __restrict__ Wqf, const float* __restrict__ Wql) {
    int i = blockIdx.x * 256 + threadIdx.x;     // 64*256 = 16384 = DD*DD
    int d = i >> 7, k = i & 127;
    int o = k * DD + d;
    g_WkT [o] = to_tf32(Wk[i]);
    g_WvT [o] = to_tf32(Wv[i]);
    g_WqfT[o] = Wqf[i];
    g_WqlT[o] = Wql[i];
}

// -------- kernel 2: k/v projection via tf32 MMA, cp.async double-buffered --------
// per CTA: 64 rows x 128 d (K and V), K=128. 8 warps = 2(m) x 4(n).
__global__ __launch_bounds__(256) void kv_mma(const float* __restrict__ enc) {
    int r0 = blockIdx.x * 64;          // 500 row tiles
    int tid = threadIdx.x, lane = tid & 31, wid = tid >> 5;
    int wm = wid >> 2, wn = wid & 3;
    int g = lane >> 2, tg = lane & 3;
    __shared__ float As[2][64][20];
    __shared__ float Bk[2][16][132];
    __shared__ float Bv[2][16][132];
    float accK[2][4][4] = {}, accV[2][4][4] = {};

    auto stage = [&](int c, int buf) {
        int kb = c * 16;
        {   // A: 256 x 16B
            int p = tid >> 2, f4 = tid & 3;
            cpa16(&As[buf][p][f4 * 4], enc + (size_t)(r0 + p) * DD + kb + f4 * 4);
        }
        for (int i = tid; i < 512; i += 256) {  // B: 512 x 16B each
            int kk = i >> 5, d4 = i & 31;
            cpa16(&Bk[buf][kk][d4 * 4], g_WkT + (kb + kk) * DD + d4 * 4);
            cpa16(&Bv[buf][kk][d4 * 4], g_WvT + (kb + kk) * DD + d4 * 4);
        }
    };

    stage(0, 0); CP_COMMIT();
    CP_WAIT0(); __syncthreads();
    for (int c = 0; c < 8; c++) {
        int cur = c & 1, nxt = cur ^ 1;
        if (c < 7) { stage(c + 1, nxt); CP_COMMIT(); }
#pragma unroll
        for (int k8 = 0; k8 < 16; k8 += 8) {
            unsigned a[2][4];
#pragma unroll
            for (int mt = 0; mt < 2; mt++) {
                int r = wm * 32 + mt * 16 + g;
                a[mt][0] = __float_as_uint(to_tf32(As[cur][r    ][k8 + tg    ]));
                a[mt][1] = __float_as_uint(to_tf32(As[cur][r + 8][k8 + tg    ]));
                a[mt][2] = __float_as_uint(to_tf32(As[cur][r    ][k8 + tg + 4]));
                a[mt][3] = __float_as_uint(to_tf32(As[cur][r + 8][k8 + tg + 4]));
            }
#pragma unroll
            for (int nt = 0; nt < 4; nt++) {
                int d = wn * 32 + nt * 8 + g;
                unsigned bk0 = __float_as_uint(Bk[cur][k8 + tg    ][d]);
                unsigned bk1 = __float_as_uint(Bk[cur][k8 + tg + 4][d]);
                unsigned bv0 = __float_as_uint(Bv[cur][k8 + tg    ][d]);
                unsigned bv1 = __float_as_uint(Bv[cur][k8 + tg + 4][d]);
#pragma unroll
                for (int mt = 0; mt < 2; mt++) {
                    mma_tf32(accK[mt][nt], a[mt], bk0, bk1);
                    mma_tf32(accV[mt][nt], a[mt], bv0, bv1);
                }
            }
        }
        if (c < 7) CP_WAIT0();
        __syncthreads();
    }
    // epilogue: exp + tf32-round, write into padded layout
#pragma unroll
    for (int mt = 0; mt < 2; mt++) {
        int rl = wm * 32 + mt * 16 + g;
        size_t prow[2];
#pragma unroll
        for (int h = 0; h < 2; h++) {
            int gr = r0 + rl + h * 8;
            int bb = gr / 1000;
            int n  = gr - bb * 1000;
            int ss = n / 125;
            int off = n - ss * 125;
            prow[h] = ((size_t)bb * NPAD + ss * 128 + off) * DD;
        }
#pragma unroll
        for (int nt = 0; nt < 4; nt++) {
            int d = wn * 32 + nt * 8 + tg * 2;
            float e0 = __expf(accK[mt][nt][0]), e1 = __expf(accK[mt][nt][1]);
            float e2 = __expf(accK[mt][nt][2]), e3 = __expf(accK[mt][nt][3]);
            *(float2*)&g_ekp [prow[0] + d] = make_float2(to_tf32(e0), to_tf32(e1));
            *(float2*)&g_ekvp[prow[0] + d] = make_float2(to_tf32(e0 * accV[mt][nt][0]), to_tf32(e1 * accV[mt][nt][1]));
            *(float2*)&g_ekp [prow[1] + d] = make_float2(to_tf32(e2), to_tf32(e3));
            *(float2*)&g_ekvp[prow[1] + d] = make_float2(to_tf32(e2 * accV[mt][nt][2]), to_tf32(e3 * accV[mt][nt][3]));
        }
    }
}

// -------- kernel 3: AFT num/den via tf32 MMA, 8-way K-split, cp.async pipelined --------
// grid (SPLIT, 2 p-halves, 32 b). per CTA: M=64(50 p) x N=128 d, K=128 (padded 125).
__global__ __launch_bounds__(256) void aft_mma(const float* __restrict__ cur_dist,
                                               const float* __restrict__ mask,
                                               const float* __restrict__ log_scale,
                                               const float* __restrict__ aft_alpha) {
    int s = blockIdx.x, ph = blockIdx.y, b = blockIdx.z;
    int tid = threadIdx.x, lane = tid & 31, wid = tid >> 5;
    int wm = wid >> 2, wn = wid & 3;
    int g = lane >> 2, tg = lane & 3;
    float c1 = log_scale[0] * aft_alpha[0];
    __shared__ float As[2][64][20];
    __shared__ float Bk[2][16][132];
    __shared__ float Bv[2][16][132];
    float accN[2][4][4] = {}, accD[2][4][4] = {};
    const float* ekB  = g_ekp  + ((size_t)b * NPAD + s * 128) * DD;
    const float* ekvB = g_ekvp + ((size_t)b * NPAD + s * 128) * DD;
    int kbase0 = s * 125;

    auto stageB = [&](int c, int buf) {
        int kb = c * 16;
        for (int i = tid; i < 512; i += 256) {
            int kk = i >> 5, d4 = i & 31;
            cpa16(&Bk[buf][kk][d4 * 4], ekB  + (kb + kk) * DD + d4 * 4);
            cpa16(&Bv[buf][kk][d4 * 4], ekvB + (kb + kk) * DD + d4 * 4);
        }
    };
    auto stageA = [&](int c, int buf) {
        int kb = c * 16;
        for (int i = tid; i < 1024; i += 256) {
            int p = i >> 4, kk = i & 15;
            float e = 0.f;
            if (p < 50 && kb + kk < 125) {
                size_t gi = ((size_t)b * PP + ph * 50 + p) * NN + kbase0 + kb + kk;
                e = to_tf32(__expf(fmaf(-c1, cur_dist[gi], mask[gi])));
            }
            As[buf][p][kk] = e;
        }
    };

    stageB(0, 0); CP_COMMIT();
    stageA(0, 0);
    CP_WAIT0(); __syncthreads();
    for (int c = 0; c < 8; c++) {
        int cur = c & 1, nxt = cur ^ 1;
        if (c < 7) { stageB(c + 1, nxt); CP_COMMIT(); stageA(c + 1, nxt); }
#pragma unroll
        for (int k8 = 0; k8 < 16; k8 += 8) {
            unsigned a[2][4];
#pragma unroll
            for (int mt = 0; mt < 2; mt++) {
                int r = wm * 32 + mt * 16 + g;
                a[mt][0] = __float_as_uint(As[cur][r    ][k8 + tg    ]);
                a[mt][1] = __float_as_uint(As[cur][r + 8][k8 + tg    ]);
                a[mt][2] = __float_as_uint(As[cur][r    ][k8 + tg + 4]);
                a[mt][3] = __float_as_uint(As[cur][r + 8][k8 + tg + 4]);
            }
#pragma unroll
            for (int nt = 0; nt < 4; nt++) {
                int d = wn * 32 + nt * 8 + g;
                unsigned bv0 = __float_as_uint(Bv[cur][k8 + tg    ][d]);
                unsigned bv1 = __float_as_uint(Bv[cur][k8 + tg + 4][d]);
                unsigned bk0 = __float_as_uint(Bk[cur][k8 + tg    ][d]);
                unsigned bk1 = __float_as_uint(Bk[cur][k8 + tg + 4][d]);
#pragma unroll
                for (int mt = 0; mt < 2; mt++) {
                    mma_tf32(accN[mt][nt], a[mt], bv0, bv1);
                    mma_tf32(accD[mt][nt], a[mt], bk0, bk1);
                }
            }
        }
        if (c < 7) CP_WAIT0();
        __syncthreads();
    }
#pragma unroll
    for (int mt = 0; mt < 2; mt++) {
        int r = wm * 32 + mt * 16 + g;
#pragma unroll
        for (int nt = 0; nt < 4; nt++) {
            int d = wn * 32 + nt * 8 + tg * 2;
            if (r < 50) {
                size_t o = (size_t)s * RD + ((size_t)b * PP + ph * 50 + r) * DD + d;
                *(float2*)&g_pnum[o] = make_float2(accN[mt][nt][0], accN[mt][nt][1]);
                *(float2*)&g_pden[o] = make_float2(accD[mt][nt][0], accD[mt][nt][1]);
            }
            if (r + 8 < 50) {
                size_t o = (size_t)s * RD + ((size_t)b * PP + ph * 50 + r + 8) * DD + d;
                *(float2*)&g_pnum[o] = make_float2(accN[mt][nt][2], accN[mt][nt][3]);
                *(float2*)&g_pden[o] = make_float2(accD[mt][nt][2], accD[mt][nt][3]);
            }
        }
    }
}

// -------- kernel 4: q = x1@WqfT + x2@WqlT -> g_aft (q only) --------
__global__ __launch_bounds__(256) void q_gemm(const float* __restrict__ x1, const float* __restrict__ x2) {
    int d0 = blockIdx.x * 32;
    int r0 = blockIdx.y * 64;
    int tid = threadIdx.x;
    int rg = tid >> 3, cg = tid & 7;
    __shared__ float x1s[64][17];
    __shared__ float x2s[64][17];
    __shared__ float wfs[16][32];
    __shared__ float wls[16][32];
    float acc[2][4] = {};
    for (int k0 = 0; k0 < 128; k0 += 16) {
        for (int i = tid; i < 1024; i += 256) {
            int r = i >> 4, kk = i & 15;
            size_t g = (size_t)(r0 + r) * DD + k0 + kk;
            x1s[r][kk] = x1[g];
            x2s[r][kk] = x2[g];
        }
        for (int i = tid; i < 512; i += 256) {
            int kk = i >> 5, c = i & 31;
            wfs[kk][c] = g_WqfT[(k0 + kk) * DD + d0 + c];
            wls[kk][c] = g_WqlT[(k0 + kk) * DD + d0 + c];
        }
        __syncthreads();
#pragma unroll
        for (int kk = 0; kk < 16; kk++) {
            float a[2], b2[2];
#pragma unroll
            for (int j = 0; j < 2; j++) { a[j] = x1s[rg * 2 + j][kk]; b2[j] = x2s[rg * 2 + j][kk]; }
            float4 wf4 = *(const float4*)&wfs[kk][cg * 4];
            float4 wl4 = *(const float4*)&wls[kk][cg * 4];
#pragma unroll
            for (int j = 0; j < 2; j++) {
                acc[j][0] += a[j] * wf4.x + b2[j] * wl4.x;
                acc[j][1] += a[j] * wf4.y + b2[j] * wl4.y;
                acc[j][2] += a[j] * wf4.z + b2[j] * wl4.z;
                acc[j][3] += a[j] * wf4.w + b2[j] * wl4.w;
            }
        }
        __syncthreads();
    }
#pragma unroll
    for (int j = 0; j < 2; j++) {
        size_t o = (size_t)(r0 + rg * 2 + j) * DD + d0 + cg * 4;
        *(float4*)&g_aft[o] = make_float4(acc[j][0], acc[j][1], acc[j][2], acc[j][3]);
    }
}

// -------- kernel 5: combine partials -> aft = sigmoid(q) * num / den --------
__global__ __launch_bounds__(256) void combine() {
    size_t i = (size_t)blockIdx.x * 256 + threadIdx.x;   // 0..102399
    size_t o = i * 4;
    float4 q4 = *(const float4*)&g_aft[o];
    float4 ns = make_float4(0.f, 0.f, 0.f, 0.f);
    float4 ds = make_float4(0.f, 0.f, 0.f, 0.f);
#pragma unroll
    for (int s = 0; s < SPLIT; s++) {
        float4 n4 = *(const float4*)&g_pnum[(size_t)s * RD + o];
        float4 d4 = *(const float4*)&g_pden[(size_t)s * RD + o];
        ns.x += n4.x; ns.y += n4.y; ns.z += n4.z; ns.w += n4.w;
        ds.x += d4.x; ds.y += d4.y; ds.z += d4.z; ds.w += d4.w;
    }
    float4 r;
    r.x = ns.x / ds.x / (1.0f + __expf(-q4.x));
    r.y = ns.y / ds.y / (1.0f + __expf(-q4.y));
    r.z = ns.z / ds.z / (1.0f + __expf(-q4.z));
    r.w = ns.w / ds.w / (1.0f + __expf(-q4.w));
    *(float4*)&g_aft[o] = r;
}

// -------- kernel 6: score = 10*tanh(aft@encT/sqrtD - c2*cur_dist) + mask (f32x2) --------
__global__ __launch_bounds__(200) void score_gemm(const float* __restrict__ enc,
                                                  const float* __restrict__ cur_dist,
                                                  const float* __restrict__ mask,
                                                  const float* __restrict__ log_scale,
                                                  const float* __restrict__ dist_alpha,
                                                  float* __restrict__ out) {
    int n0 = blockIdx.x * 40;
    int b  = blockIdx.y;
    int tid = threadIdx.x;
    int pg = tid / 10, cg = tid - pg * 10;
    __shared__ __align__(16) float2 afts2[100][16];
    __shared__ __align__(16) float  encs[16][44];
    unsigned long long acc[5][2] = {};
    for (int k0 = 0; k0 < 128; k0 += 16) {
        for (int i = tid; i < 1600; i += 200) {
            int p = i >> 4, kk = i & 15;
            float v = g_aft[((size_t)b * PP + p) * DD + k0 + kk];
            afts2[p][kk] = make_float2(v, v);
        }
        for (int i = tid; i < 640; i += 200) {
            int nn = i >> 4, kk = i & 15;
            encs[kk][nn] = enc[((size_t)b * NN + n0 + nn) * DD + k0 + kk];
        }
        __syncthreads();
#pragma unroll
        for (int kk = 0; kk < 16; kk++) {
            unsigned long long a[5];
#pragma unroll
            for (int j = 0; j < 5; j++) a[j] = *(const unsigned long long*)&afts2[pg * 5 + j][kk];
            ulonglong2 e2 = *(const ulonglong2*)&encs[kk][cg * 4];
#pragma unroll
            for (int j = 0; j < 5; j++) {
                fma2(acc[j][0], a[j], e2.x);
                fma2(acc[j][1], a[j], e2.y);
            }
        }
        __syncthreads();
    }
    float c2 = log_scale[0] * dist_alpha[0];
    const float inv_sqrt_d = 0.08838834764831845f;
#pragma unroll
    for (int j = 0; j < 5; j++) {
        int p = pg * 5 + j;
        size_t base = ((size_t)b * PP + p) * NN + n0 + cg * 4;
        float4 cd = *(const float4*)(cur_dist + base);
        float4 mk = *(const float4*)(mask + base);
        float2 a01 = unpk(acc[j][0]), a23 = unpk(acc[j][1]);
        float4 r;
        r.x = 10.0f * tanhf(a01.x * inv_sqrt_d - c2 * cd.x) + mk.x;
        r.y = 10.0f * tanhf(a01.y * inv_sqrt_d - c2 * cd.y) + mk.y;
        r.z = 10.0f * tanhf(a23.x * inv_sqrt_d - c2 * cd.z) + mk.z;
        r.w = 10.0f * tanhf(a23.y * inv_sqrt_d - c2 * cd.w) + mk.w;
        *(float4*)(out + base) = r;
    }
}

// -------- kernel 7: row softmax over N=1000, in place --------
__global__ __launch_bounds__(256) void softmax_rows(float* __restrict__ out) {
    size_t row = blockIdx.x;
    float* p = out + row * NN;
    int tid = threadIdx.x;
    float v[4];
    int cnt = 0;
    float mx = -3.0e38f;
    for (int i = tid; i < NN; i += 256) { v[cnt] = p[i]; mx = fmaxf(mx, v[cnt]); cnt++; }
#pragma unroll
    for (int o = 16; o; o >>= 1) mx = fmaxf(mx, __shfl_xor_sync(0xffffffffu, mx, o));
    __shared__ float sm[8], ss[8];
    int w = tid >> 5, l = tid & 31;
    if (l == 0) sm[w] = mx;
    __syncthreads();
    float m = sm[0];
#pragma unroll
    for (int i = 1; i < 8; i++) m = fmaxf(m, sm[i]);
    float s = 0.0f;
    for (int c = 0; c < cnt; c++) { v[c] = __expf(v[c] - m); s += v[c]; }
#pragma unroll
    for (int o = 16; o; o >>= 1) s += __shfl_xor_sync(0xffffffffu, s, o);
    if (l == 0) ss[w] = s;
    __syncthreads();
    float tot = 0.0f;
#pragma unroll
    for (int i = 0; i < 8; i++) tot += ss[i];
    float inv = 1.0f / tot;
    cnt = 0;
    for (int i = tid; i < NN; i += 256) { p[i] = v[cnt] * inv; cnt++; }
}

extern "C" void kernel_launch(void* const* d_in, const int* in_sizes, int n_in,
                              void* d_out, int out_size) {
    const float* enc        = (const float*)d_in[0];   // [B,N,D]
    const float* q1         = (const float*)d_in[1];   // [B,P,D]
    const float* last       = (const float*)d_in[2];   // [B,P,D]
    const float* cur_dist   = (const float*)d_in[3];   // [B,P,N]
    const float* ninf_mask  = (const float*)d_in[4];   // [B,P,N]
    const float* log_scale  = (const float*)d_in[5];   // [1]
    const float* Wq_first   = (const float*)d_in[6];   // [D,D]
    const float* Wq_last    = (const float*)d_in[7];   // [D,D]
    const float* Wk         = (const float*)d_in[8];   // [D,D]
    const float* Wv         = (const float*)d_in[9];   // [D,D]
    const float* dist_alpha = (const float*)d_in[10];  // [1]
    const float* aft_alpha  = (const float*)d_in[11];  // [1]
    float* out = (float*)d_out;                        // [B,P,N]

    transpose_w<<<64, 256>>>(Wk, Wv, Wq_first, Wq_last);
    kv_mma<<<500, 256>>>(enc);
    q_gemm<<<dim3(4, 50), 256>>>(q1, last);
    aft_mma<<<dim3(SPLIT, 2, BB), 256>>>(cur_dist, ninf_mask, log_scale, aft_alpha);
    combine<<<400, 256>>>();
    score_gemm<<<dim3(25, 32), 200>>>(enc, cur_dist, ninf_mask, log_scale, dist_alpha, out);
    softmax_rows<<<3200, 256>>>(out);
}

// round 13
// speedup vs baseline: 2.0259x; 1.3636x over previous
#include <cuda_runtime.h>
#include <math.h>

// Problem dims
#define BB 32
#define PP 100
#define NN 1000
#define DD 128
#define SPLIT 8
#define ROWS (BB*PP)           // 3200
#define RD   ((size_t)ROWS*DD) // 409600
#define NPAD (SPLIT*128)       // 1024 padded n per batch

// -------- device scratch (static, allocation-free) --------
__device__ float g_WkT [DD*DD];   // tf32-rounded
__device__ float g_WvT [DD*DD];   // tf32-rounded
__device__ float g_WqfT[DD*DD];
__device__ float g_WqlT[DD*DD];
__device__ float g_ekp [(size_t)BB*NPAD*DD];  // exp(k), tf32, padded (pads stay 0)
__device__ float g_ekvp[(size_t)BB*NPAD*DD];  // exp(k)*v, tf32, padded
__device__ float g_pnum[SPLIT*RD];            // K-split partials
__device__ float g_pden[SPLIT*RD];
__device__ float g_aft [RD];                  // q, then aft (tf32-rounded)

// -------- tf32 mma helpers --------
__device__ __forceinline__ float to_tf32(float x) {
    asm("cvt.rna.tf32.f32 %0, %1;" : "=f"(x) : "f"(x));
    return x;
}
__device__ __forceinline__ void mma_tf32(float c[4], const unsigned a[4], unsigned b0, unsigned b1) {
    asm volatile("mma.sync.aligned.m16n8k8.row.col.f32.tf32.tf32.f32 "
                 "{%0,%1,%2,%3}, {%4,%5,%6,%7}, {%8,%9}, {%0,%1,%2,%3};"
                 : "+f"(c[0]), "+f"(c[1]), "+f"(c[2]), "+f"(c[3])
                 : "r"(a[0]), "r"(a[1]), "r"(a[2]), "r"(a[3]), "r"(b0), "r"(b1));
}

// -------- cp.async helpers --------
__device__ __forceinline__ void cpa16(void* dst_smem, const float* src) {
    unsigned s = (unsigned)__cvta_generic_to_shared(dst_smem);
    asm volatile("cp.async.cg.shared.global [%0], [%1], 16;\n" :: "r"(s), "l"(src));
}
#define CP_COMMIT() asm volatile("cp.async.commit_group;\n" ::: "memory")
#define CP_WAIT0()  asm volatile("cp.async.wait_group 0;\n" ::: "memory")
#define CP_WAIT1()  asm volatile("cp.async.wait_group 1;\n" ::: "memory")

// -------- kernel 1: transpose weights (Wk/Wv pre-rounded to tf32) --------
__global__ void transpose_w(const float* __restrict__ Wk, const float* __restrict__ Wv,
                            const float* __restrict__ Wqf, const float* __restrict__ Wql) {
    int i = blockIdx.x * 256 + threadIdx.x;     // 64*256 = 16384
    int d = i >> 7, k = i & 127;
    int o = k * DD + d;
    g_WkT [o] = to_tf32(Wk[i]);
    g_WvT [o] = to_tf32(Wv[i]);
    g_WqfT[o] = Wqf[i];
    g_WqlT[o] = Wql[i];
}

// -------- kernel 2: k/v projection via tf32 MMA, 3-stage cp.async ring --------
__global__ __launch_bounds__(256) void kv_mma(const float* __restrict__ enc) {
    int r0 = blockIdx.x * 64;          // 500 row tiles
    int tid = threadIdx.x, lane = tid & 31, wid = tid >> 5;
    int wm = wid >> 2, wn = wid & 3;
    int g = lane >> 2, tg = lane & 3;
    __shared__ float As[3][64][20];
    __shared__ float Bk[3][16][136];
    __shared__ float Bv[3][16][136];
    float accK[2][4][4] = {}, accV[2][4][4] = {};

    auto stage = [&](int c, int buf) {
        int kb = c * 16;
        {
            int p = tid >> 2, f4 = tid & 3;
            cpa16(&As[buf][p][f4 * 4], enc + (size_t)(r0 + p) * DD + kb + f4 * 4);
        }
        for (int i = tid; i < 512; i += 256) {
            int kk = i >> 5, d4 = i & 31;
            cpa16(&Bk[buf][kk][d4 * 4], g_WkT + (kb + kk) * DD + d4 * 4);
            cpa16(&Bv[buf][kk][d4 * 4], g_WvT + (kb + kk) * DD + d4 * 4);
        }
    };

    stage(0, 0); CP_COMMIT();
    stage(1, 1); CP_COMMIT();
    for (int c = 0; c < 8; c++) {
        if (c < 7) { CP_WAIT1(); } else { CP_WAIT0(); }
        __syncthreads();
        int cur = c % 3;
        if (c < 6) { stage(c + 2, (c + 2) % 3); CP_COMMIT(); }
#pragma unroll
        for (int k8 = 0; k8 < 16; k8 += 8) {
            unsigned a[2][4];
#pragma unroll
            for (int mt = 0; mt < 2; mt++) {
                int r = wm * 32 + mt * 16 + g;
                a[mt][0] = __float_as_uint(to_tf32(As[cur][r    ][k8 + tg    ]));
                a[mt][1] = __float_as_uint(to_tf32(As[cur][r + 8][k8 + tg    ]));
                a[mt][2] = __float_as_uint(to_tf32(As[cur][r    ][k8 + tg + 4]));
                a[mt][3] = __float_as_uint(to_tf32(As[cur][r + 8][k8 + tg + 4]));
            }
#pragma unroll
            for (int nt = 0; nt < 4; nt++) {
                int d = wn * 32 + nt * 8 + g;
                unsigned bk0 = __float_as_uint(Bk[cur][k8 + tg    ][d]);
                unsigned bk1 = __float_as_uint(Bk[cur][k8 + tg + 4][d]);
                unsigned bv0 = __float_as_uint(Bv[cur][k8 + tg    ][d]);
                unsigned bv1 = __float_as_uint(Bv[cur][k8 + tg + 4][d]);
#pragma unroll
                for (int mt = 0; mt < 2; mt++) {
                    mma_tf32(accK[mt][nt], a[mt], bk0, bk1);
                    mma_tf32(accV[mt][nt], a[mt], bv0, bv1);
                }
            }
        }
    }
#pragma unroll
    for (int mt = 0; mt < 2; mt++) {
        int rl = wm * 32 + mt * 16 + g;
        size_t prow[2];
#pragma unroll
        for (int h = 0; h < 2; h++) {
            int gr = r0 + rl + h * 8;
            int bb = gr / 1000;
            int n  = gr - bb * 1000;
            int ss = n / 125;
            int off = n - ss * 125;
            prow[h] = ((size_t)bb * NPAD + ss * 128 + off) * DD;
        }
#pragma unroll
        for (int nt = 0; nt < 4; nt++) {
            int d = wn * 32 + nt * 8 + tg * 2;
            float e0 = __expf(accK[mt][nt][0]), e1 = __expf(accK[mt][nt][1]);
            float e2 = __expf(accK[mt][nt][2]), e3 = __expf(accK[mt][nt][3]);
            *(float2*)&g_ekp [prow[0] + d] = make_float2(to_tf32(e0), to_tf32(e1));
            *(float2*)&g_ekvp[prow[0] + d] = make_float2(to_tf32(e0 * accV[mt][nt][0]), to_tf32(e1 * accV[mt][nt][1]));
            *(float2*)&g_ekp [prow[1] + d] = make_float2(to_tf32(e2), to_tf32(e3));
            *(float2*)&g_ekvp[prow[1] + d] = make_float2(to_tf32(e2 * accV[mt][nt][2]), to_tf32(e3 * accV[mt][nt][3]));
        }
    }
}

// -------- kernel 3: AFT num/den via tf32 MMA, 8-way K-split, 3-stage ring --------
__global__ __launch_bounds__(256) void aft_mma(const float* __restrict__ cur_dist,
                                               const float* __restrict__ mask,
                                               const float* __restrict__ log_scale,
                                               const float* __restrict__ aft_alpha) {
    int s = blockIdx.x, ph = blockIdx.y, b = blockIdx.z;
    int tid = threadIdx.x, lane = tid & 31, wid = tid >> 5;
    int wm = wid >> 2, wn = wid & 3;
    int g = lane >> 2, tg = lane & 3;
    float c1 = log_scale[0] * aft_alpha[0];
    __shared__ float As[3][64][20];
    __shared__ float Bk[3][16][136];
    __shared__ float Bv[3][16][136];
    float accN[2][4][4] = {}, accD[2][4][4] = {};
    const float* ekB  = g_ekp  + ((size_t)b * NPAD + s * 128) * DD;
    const float* ekvB = g_ekvp + ((size_t)b * NPAD + s * 128) * DD;
    int kbase0 = s * 125;

    auto stageB = [&](int c, int buf) {
        int kb = c * 16;
        for (int i = tid; i < 512; i += 256) {
            int kk = i >> 5, d4 = i & 31;
            cpa16(&Bk[buf][kk][d4 * 4], ekB  + (kb + kk) * DD + d4 * 4);
            cpa16(&Bv[buf][kk][d4 * 4], ekvB + (kb + kk) * DD + d4 * 4);
        }
    };
    auto stageA = [&](int c, int buf) {
        int kb = c * 16;
        for (int i = tid; i < 1024; i += 256) {
            int p = i >> 4, kk = i & 15;
            float e = 0.f;
            if (p < 50 && kb + kk < 125) {
                size_t gi = ((size_t)b * PP + ph * 50 + p) * NN + kbase0 + kb + kk;
                e = to_tf32(__expf(fmaf(-c1, cur_dist[gi], mask[gi])));
            }
            As[buf][p][kk] = e;
        }
    };

    stageB(0, 0); CP_COMMIT(); stageA(0, 0);
    stageB(1, 1); CP_COMMIT(); stageA(1, 1);
    for (int c = 0; c < 8; c++) {
        if (c < 7) { CP_WAIT1(); } else { CP_WAIT0(); }
        __syncthreads();
        int cur = c % 3;
        if (c < 6) { stageB(c + 2, (c + 2) % 3); CP_COMMIT(); stageA(c + 2, (c + 2) % 3); }
#pragma unroll
        for (int k8 = 0; k8 < 16; k8 += 8) {
            unsigned a[2][4];
#pragma unroll
            for (int mt = 0; mt < 2; mt++) {
                int r = wm * 32 + mt * 16 + g;
                a[mt][0] = __float_as_uint(As[cur][r    ][k8 + tg    ]);
                a[mt][1] = __float_as_uint(As[cur][r + 8][k8 + tg    ]);
                a[mt][2] = __float_as_uint(As[cur][r    ][k8 + tg + 4]);
                a[mt][3] = __float_as_uint(As[cur][r + 8][k8 + tg + 4]);
            }
#pragma unroll
            for (int nt = 0; nt < 4; nt++) {
                int d = wn * 32 + nt * 8 + g;
                unsigned bv0 = __float_as_uint(Bv[cur][k8 + tg    ][d]);
                unsigned bv1 = __float_as_uint(Bv[cur][k8 + tg + 4][d]);
                unsigned bk0 = __float_as_uint(Bk[cur][k8 + tg    ][d]);
                unsigned bk1 = __float_as_uint(Bk[cur][k8 + tg + 4][d]);
#pragma unroll
                for (int mt = 0; mt < 2; mt++) {
                    mma_tf32(accN[mt][nt], a[mt], bv0, bv1);
                    mma_tf32(accD[mt][nt], a[mt], bk0, bk1);
                }
            }
        }
    }
#pragma unroll
    for (int mt = 0; mt < 2; mt++) {
        int r = wm * 32 + mt * 16 + g;
#pragma unroll
        for (int nt = 0; nt < 4; nt++) {
            int d = wn * 32 + nt * 8 + tg * 2;
            if (r < 50) {
                size_t o = (size_t)s * RD + ((size_t)b * PP + ph * 50 + r) * DD + d;
                *(float2*)&g_pnum[o] = make_float2(accN[mt][nt][0], accN[mt][nt][1]);
                *(float2*)&g_pden[o] = make_float2(accD[mt][nt][0], accD[mt][nt][1]);
            }
            if (r + 8 < 50) {
                size_t o = (size_t)s * RD + ((size_t)b * PP + ph * 50 + r + 8) * DD + d;
                *(float2*)&g_pnum[o] = make_float2(accN[mt][nt][2], accN[mt][nt][3]);
                *(float2*)&g_pden[o] = make_float2(accD[mt][nt][2], accD[mt][nt][3]);
            }
        }
    }
}

// -------- kernel 4: q = x1@WqfT + x2@WqlT -> g_aft (q only) --------
__global__ __launch_bounds__(256) void q_gemm(const float* __restrict__ x1, const float* __restrict__ x2) {
    int d0 = blockIdx.x * 32;
    int r0 = blockIdx.y * 64;
    int tid = threadIdx.x;
    int rg = tid >> 3, cg = tid & 7;
    __shared__ float x1s[64][17];
    __shared__ float x2s[64][17];
    __shared__ float wfs[16][32];
    __shared__ float wls[16][32];
    float acc[2][4] = {};
    for (int k0 = 0; k0 < 128; k0 += 16) {
        for (int i = tid; i < 1024; i += 256) {
            int r = i >> 4, kk = i & 15;
            size_t g = (size_t)(r0 + r) * DD + k0 + kk;
            x1s[r][kk] = x1[g];
            x2s[r][kk] = x2[g];
        }
        for (int i = tid; i < 512; i += 256) {
            int kk = i >> 5, c = i & 31;
            wfs[kk][c] = g_WqfT[(k0 + kk) * DD + d0 + c];
            wls[kk][c] = g_WqlT[(k0 + kk) * DD + d0 + c];
        }
        __syncthreads();
#pragma unroll
        for (int kk = 0; kk < 16; kk++) {
            float a[2], b2[2];
#pragma unroll
            for (int j = 0; j < 2; j++) { a[j] = x1s[rg * 2 + j][kk]; b2[j] = x2s[rg * 2 + j][kk]; }
            float4 wf4 = *(const float4*)&wfs[kk][cg * 4];
            float4 wl4 = *(const float4*)&wls[kk][cg * 4];
#pragma unroll
            for (int j = 0; j < 2; j++) {
                acc[j][0] += a[j] * wf4.x + b2[j] * wl4.x;
                acc[j][1] += a[j] * wf4.y + b2[j] * wl4.y;
                acc[j][2] += a[j] * wf4.z + b2[j] * wl4.z;
                acc[j][3] += a[j] * wf4.w + b2[j] * wl4.w;
            }
        }
        __syncthreads();
    }
#pragma unroll
    for (int j = 0; j < 2; j++) {
        size_t o = (size_t)(r0 + rg * 2 + j) * DD + d0 + cg * 4;
        *(float4*)&g_aft[o] = make_float4(acc[j][0], acc[j][1], acc[j][2], acc[j][3]);
    }
}

// -------- kernel 5: combine -> aft = tf32(sigmoid(q) * num / den) --------
__global__ __launch_bounds__(256) void combine() {
    size_t i = (size_t)blockIdx.x * 256 + threadIdx.x;   // 0..102399
    size_t o = i * 4;
    float4 q4 = *(const float4*)&g_aft[o];
    float4 ns = make_float4(0.f, 0.f, 0.f, 0.f);
    float4 ds = make_float4(0.f, 0.f, 0.f, 0.f);
#pragma unroll
    for (int s = 0; s < SPLIT; s++) {
        float4 n4 = *(const float4*)&g_pnum[(size_t)s * RD + o];
        float4 d4 = *(const float4*)&g_pden[(size_t)s * RD + o];
        ns.x += n4.x; ns.y += n4.y; ns.z += n4.z; ns.w += n4.w;
        ds.x += d4.x; ds.y += d4.y; ds.z += d4.z; ds.w += d4.w;
    }
    float4 r;
    r.x = to_tf32(ns.x / ds.x / (1.0f + __expf(-q4.x)));
    r.y = to_tf32(ns.y / ds.y / (1.0f + __expf(-q4.y)));
    r.z = to_tf32(ns.z / ds.z / (1.0f + __expf(-q4.z)));
    r.w = to_tf32(ns.w / ds.w / (1.0f + __expf(-q4.w)));
    *(float4*)&g_aft[o] = r;
}

// -------- kernel 6: score via tf32 MMA; M=nodes, N=p; epilogue writes exp(logit-10) --------
// grid (16 node-tiles of 64, 32 b), 256 thr, warps 2m x 4n; per warp mt=2, nt=4
__global__ __launch_bounds__(256) void score_mma(const float* __restrict__ enc,
                                                 const float* __restrict__ cur_dist,
                                                 const float* __restrict__ mask,
                                                 const float* __restrict__ log_scale,
                                                 const float* __restrict__ dist_alpha,
                                                 float* __restrict__ out) {
    int n0 = blockIdx.x * 64;
    int b  = blockIdx.y;
    int tid = threadIdx.x, lane = tid & 31, wid = tid >> 5;
    int wm = wid >> 2, wn = wid & 3;
    int g = lane >> 2, tg = lane & 3;
    __shared__ float As[3][64][20];    // enc tile [node][k]
    __shared__ float Bs[3][128][20];   // aft tile [p][k] (k-contiguous = col-major B)
    float acc[2][4][4] = {};

    auto stage = [&](int c, int buf) {
        int kb = c * 16;
        {   // A: 64 nodes x 16 k
            int nn = tid >> 2, f4 = tid & 3;
            int node = n0 + nn; if (node > 999) node = 999;
            cpa16(&As[buf][nn][f4 * 4], enc + ((size_t)b * NN + node) * DD + kb + f4 * 4);
        }
        for (int i = tid; i < 512; i += 256) {   // B: 128 p x 16 k
            int p = i >> 2, f4 = i & 3;
            int pc = p > 99 ? 99 : p;
            cpa16(&Bs[buf][p][f4 * 4], g_aft + ((size_t)b * PP + pc) * DD + kb + f4 * 4);
        }
    };

    stage(0, 0); CP_COMMIT();
    stage(1, 1); CP_COMMIT();
    for (int c = 0; c < 8; c++) {
        if (c < 7) { CP_WAIT1(); } else { CP_WAIT0(); }
        __syncthreads();
        int cur = c % 3;
        if (c < 6) { stage(c + 2, (c + 2) % 3); CP_COMMIT(); }
#pragma unroll
        for (int k8 = 0; k8 < 16; k8 += 8) {
            unsigned a[2][4];
#pragma unroll
            for (int mt = 0; mt < 2; mt++) {
                int r = wm * 32 + mt * 16 + g;
                a[mt][0] = __float_as_uint(to_tf32(As[cur][r    ][k8 + tg    ]));
                a[mt][1] = __float_as_uint(to_tf32(As[cur][r + 8][k8 + tg    ]));
                a[mt][2] = __float_as_uint(to_tf32(As[cur][r    ][k8 + tg + 4]));
                a[mt][3] = __float_as_uint(to_tf32(As[cur][r + 8][k8 + tg + 4]));
            }
#pragma unroll
            for (int nt = 0; nt < 4; nt++) {
                int p = wn * 32 + nt * 8 + g;
                unsigned b0 = __float_as_uint(Bs[cur][p][k8 + tg    ]);
                unsigned b1 = __float_as_uint(Bs[cur][p][k8 + tg + 4]);
#pragma unroll
                for (int mt = 0; mt < 2; mt++) mma_tf32(acc[mt][nt], a[mt], b0, b1);
            }
        }
    }
    float c2 = log_scale[0] * dist_alpha[0];
    const float inv_sqrt_d = 0.08838834764831845f;   // 1/sqrt(128)
#pragma unroll
    for (int mt = 0; mt < 2; mt++) {
#pragma unroll
        for (int nt = 0; nt < 4; nt++) {
#pragma unroll
            for (int e = 0; e < 4; e++) {
                int node = n0 + wm * 32 + mt * 16 + g + (e >> 1) * 8;
                int p    = wn * 32 + nt * 8 + tg * 2 + (e & 1);
                if (node < 1000 && p < 100) {
                    size_t o = ((size_t)b * PP + p) * NN + node;
                    float sc = acc[mt][nt][e] * inv_sqrt_d - c2 * cur_dist[o];
                    out[o] = __expf(10.0f * tanhf(sc) - 10.0f + mask[o]);
                }
            }
        }
    }
}

// -------- kernel 7: normalize rows (out already holds exp(logit-10) > 0) --------
__global__ __launch_bounds__(256) void norm_rows(float* __restrict__ out) {
    size_t row = blockIdx.x;
    float* p = out + row * NN;
    int tid = threadIdx.x;
    float v[4];
    int cnt = 0;
    float s = 0.0f;
    for (int i = tid; i < NN; i += 256) { v[cnt] = p[i]; s += v[cnt]; cnt++; }
#pragma unroll
    for (int o = 16; o; o >>= 1) s += __shfl_xor_sync(0xffffffffu, s, o);
    __shared__ float ss[8];
    int w = tid >> 5, l = tid & 31;
    if (l == 0) ss[w] = s;
    __syncthreads();
    float tot = 0.0f;
#pragma unroll
    for (int i = 0; i < 8; i++) tot += ss[i];
    float inv = 1.0f / tot;
    cnt = 0;
    for (int i = tid; i < NN; i += 256) { p[i] = v[cnt] * inv; cnt++; }
}

extern "C" void kernel_launch(void* const* d_in, const int* in_sizes, int n_in,
                              void* d_out, int out_size) {
    const float* enc        = (const float*)d_in[0];   // [B,N,D]
    const float* q1         = (const float*)d_in[1];   // [B,P,D]
    const float* last       = (const float*)d_in[2];   // [B,P,D]
    const float* cur_dist   = (const float*)d_in[3];   // [B,P,N]
    const float* ninf_mask  = (const float*)d_in[4];   // [B,P,N]
    const float* log_scale  = (const float*)d_in[5];   // [1]
    const float* Wq_first   = (const float*)d_in[6];   // [D,D]
    const float* Wq_last    = (const float*)d_in[7];   // [D,D]
    const float* Wk         = (const float*)d_in[8];   // [D,D]
    const float* Wv         = (const float*)d_in[9];   // [D,D]
    const float* dist_alpha = (const float*)d_in[10];  // [1]
    const float* aft_alpha  = (const float*)d_in[11];  // [1]
    float* out = (float*)d_out;                        // [B,P,N]

    transpose_w<<<64, 256>>>(Wk, Wv, Wq_first, Wq_last);
    kv_mma<<<500, 256>>>(enc);
    q_gemm<<<dim3(4, 50), 256>>>(q1, last);
    aft_mma<<<dim3(SPLIT, 2, BB), 256>>>(cur_dist, ninf_mask, log_scale, aft_alpha);
    combine<<<400, 256>>>();
    score_mma<<<dim3(16, 32), 256>>>(enc, cur_dist, ninf_mask, log_scale, dist_alpha, out);
    norm_rows<<<3200, 256>>>(out);
}

// round 15
// speedup vs baseline: 2.2273x; 1.0994x over previous
#include <cuda_runtime.h>
#include <math.h>

// Problem dims
#define BB 32
#define PP 100
#define NN 1000
#define DD 128
#define SPLIT 8
#define ROWS (BB*PP)           // 3200
#define RD   ((size_t)ROWS*DD) // 409600
#define NPAD (SPLIT*128)       // 1024 padded n per batch

// -------- device scratch (static, allocation-free) --------
__device__ float g_WkT [DD*DD];   // tf32-rounded
__device__ float g_WvT [DD*DD];   // tf32-rounded
__device__ float g_WqfT[DD*DD];
__device__ float g_WqlT[DD*DD];
__device__ float g_ekp [(size_t)BB*NPAD*DD];  // exp(k), tf32, padded (pads stay 0)
__device__ float g_ekvp[(size_t)BB*NPAD*DD];  // exp(k)*v, tf32, padded
__device__ float g_pnum[SPLIT*RD];            // K-split partials
__device__ float g_pden[SPLIT*RD];
__device__ float g_aft [RD];                  // q, then aft (tf32-rounded)

// -------- tf32 mma helpers --------
__device__ __forceinline__ float to_tf32(float x) {
    asm("cvt.rna.tf32.f32 %0, %1;" : "=f"(x) : "f"(x));
    return x;
}
__device__ __forceinline__ void mma_tf32(float c[4], const unsigned a[4], unsigned b0, unsigned b1) {
    asm volatile("mma.sync.aligned.m16n8k8.row.col.f32.tf32.tf32.f32 "
                 "{%0,%1,%2,%3}, {%4,%5,%6,%7}, {%8,%9}, {%0,%1,%2,%3};"
                 : "+f"(c[0]), "+f"(c[1]), "+f"(c[2]), "+f"(c[3])
                 : "r"(a[0]), "r"(a[1]), "r"(a[2]), "r"(a[3]), "r"(b0), "r"(b1));
}

// -------- cp.async helpers --------
__device__ __forceinline__ void cpa16(void* dst_smem, const float* src) {
    unsigned s = (unsigned)__cvta_generic_to_shared(dst_smem);
    asm volatile("cp.async.cg.shared.global [%0], [%1], 16;\n" :: "r"(s), "l"(src));
}
#define CP_COMMIT() asm volatile("cp.async.commit_group;\n" ::: "memory")
#define CP_WAIT0()  asm volatile("cp.async.wait_group 0;\n" ::: "memory")
#define CP_WAIT1()  asm volatile("cp.async.wait_group 1;\n" ::: "memory")

// -------- kernel 1: transpose weights (Wk/Wv pre-rounded to tf32) --------
__global__ void transpose_w(const float* __restrict__ Wk, const float* __restrict__ Wv,
                            const float* __restrict__ Wqf, const float* __restrict__ Wql) {
    int i = blockIdx.x * 256 + threadIdx.x;     // 64*256 = 16384
    int d = i >> 7, k = i & 127;
    int o = k * DD + d;
    g_WkT [o] = to_tf32(Wk[i]);
    g_WvT [o] = to_tf32(Wv[i]);
    g_WqfT[o] = Wqf[i];
    g_WqlT[o] = Wql[i];
}

// -------- kernel 2: k/v projection via tf32 MMA, 3-stage cp.async ring --------
__global__ __launch_bounds__(256) void kv_mma(const float* __restrict__ enc) {
    int r0 = blockIdx.x * 64;          // 500 row tiles
    int tid = threadIdx.x, lane = tid & 31, wid = tid >> 5;
    int wm = wid >> 2, wn = wid & 3;
    int g = lane >> 2, tg = lane & 3;
    __shared__ float As[3][64][20];
    __shared__ float Bk[3][16][136];
    __shared__ float Bv[3][16][136];
    float accK[2][4][4] = {}, accV[2][4][4] = {};

    auto stage = [&](int c, int buf) {
        int kb = c * 16;
        {
            int p = tid >> 2, f4 = tid & 3;
            cpa16(&As[buf][p][f4 * 4], enc + (size_t)(r0 + p) * DD + kb + f4 * 4);
        }
        for (int i = tid; i < 512; i += 256) {
            int kk = i >> 5, d4 = i & 31;
            cpa16(&Bk[buf][kk][d4 * 4], g_WkT + (kb + kk) * DD + d4 * 4);
            cpa16(&Bv[buf][kk][d4 * 4], g_WvT + (kb + kk) * DD + d4 * 4);
        }
    };

    stage(0, 0); CP_COMMIT();
    stage(1, 1); CP_COMMIT();
    for (int c = 0; c < 8; c++) {
        if (c < 7) { CP_WAIT1(); } else { CP_WAIT0(); }
        __syncthreads();
        int cur = c % 3;
        if (c < 6) { stage(c + 2, (c + 2) % 3); CP_COMMIT(); }
#pragma unroll
        for (int k8 = 0; k8 < 16; k8 += 8) {
            unsigned a[2][4];
#pragma unroll
            for (int mt = 0; mt < 2; mt++) {
                int r = wm * 32 + mt * 16 + g;
                a[mt][0] = __float_as_uint(to_tf32(As[cur][r    ][k8 + tg    ]));
                a[mt][1] = __float_as_uint(to_tf32(As[cur][r + 8][k8 + tg    ]));
                a[mt][2] = __float_as_uint(to_tf32(As[cur][r    ][k8 + tg + 4]));
                a[mt][3] = __float_as_uint(to_tf32(As[cur][r + 8][k8 + tg + 4]));
            }
#pragma unroll
            for (int nt = 0; nt < 4; nt++) {
                int d = wn * 32 + nt * 8 + g;
                unsigned bk0 = __float_as_uint(Bk[cur][k8 + tg    ][d]);
                unsigned bk1 = __float_as_uint(Bk[cur][k8 + tg + 4][d]);
                unsigned bv0 = __float_as_uint(Bv[cur][k8 + tg    ][d]);
                unsigned bv1 = __float_as_uint(Bv[cur][k8 + tg + 4][d]);
#pragma unroll
                for (int mt = 0; mt < 2; mt++) {
                    mma_tf32(accK[mt][nt], a[mt], bk0, bk1);
                    mma_tf32(accV[mt][nt], a[mt], bv0, bv1);
                }
            }
        }
    }
    // epilogue: exp + tf32-round into padded layout (128-chunked: ss = n>>7)
#pragma unroll
    for (int mt = 0; mt < 2; mt++) {
        int rl = wm * 32 + mt * 16 + g;
        size_t prow[2];
#pragma unroll
        for (int h = 0; h < 2; h++) {
            int gr = r0 + rl + h * 8;
            int bb = gr / 1000;
            int n  = gr - bb * 1000;
            prow[h] = ((size_t)bb * NPAD + n) * DD;   // n < 1000 <= NPAD; ss*128+off == n
        }
#pragma unroll
        for (int nt = 0; nt < 4; nt++) {
            int d = wn * 32 + nt * 8 + tg * 2;
            float e0 = __expf(accK[mt][nt][0]), e1 = __expf(accK[mt][nt][1]);
            float e2 = __expf(accK[mt][nt][2]), e3 = __expf(accK[mt][nt][3]);
            *(float2*)&g_ekp [prow[0] + d] = make_float2(to_tf32(e0), to_tf32(e1));
            *(float2*)&g_ekvp[prow[0] + d] = make_float2(to_tf32(e0 * accV[mt][nt][0]), to_tf32(e1 * accV[mt][nt][1]));
            *(float2*)&g_ekp [prow[1] + d] = make_float2(to_tf32(e2), to_tf32(e3));
            *(float2*)&g_ekvp[prow[1] + d] = make_float2(to_tf32(e2 * accV[mt][nt][2]), to_tf32(e3 * accV[mt][nt][3]));
        }
    }
}

// -------- kernel 3: AFT num/den via tf32 MMA; raw A tiles cp.async-pipelined --------
// grid (SPLIT, 2 p-halves, 32 b). per CTA: M=64(50 p) x N=128 d, K=128 (split 7: 104 valid).
__global__ __launch_bounds__(256) void aft_mma(const float* __restrict__ cur_dist,
                                               const float* __restrict__ mask,
                                               const float* __restrict__ log_scale,
                                               const float* __restrict__ aft_alpha) {
    int s = blockIdx.x, ph = blockIdx.y, b = blockIdx.z;
    int tid = threadIdx.x, lane = tid & 31, wid = tid >> 5;
    int wm = wid >> 2, wn = wid & 3;
    int g = lane >> 2, tg = lane & 3;
    float c1 = log_scale[0] * aft_alpha[0];
    int valid = (s == SPLIT - 1) ? (NN - (SPLIT - 1) * 128) : 128;   // 104 or 128
    int maxcol = (valid - 4) & ~3;                                   // 100 or 124 (16B-aligned)
    __shared__ float As[64][20];          // single-buffer, exp'd per chunk
    __shared__ float rawC[3][50][20];     // raw cur_dist tiles
    __shared__ float rawM[3][50][20];     // raw mask tiles
    __shared__ float Bk[3][16][136];
    __shared__ float Bv[3][16][136];
    float accN[2][4][4] = {}, accD[2][4][4] = {};
    const float* ekB  = g_ekp  + ((size_t)b * NPAD + s * 128) * DD;
    const float* ekvB = g_ekvp + ((size_t)b * NPAD + s * 128) * DD;
    const float* cdB  = cur_dist + ((size_t)b * PP + ph * 50) * NN + s * 128;  // 512B-aligned
    const float* mkB  = mask     + ((size_t)b * PP + ph * 50) * NN + s * 128;

    // zero As once (rows 50-63 feed discarded output rows)
    for (int i = tid; i < 64 * 20; i += 256) ((float*)As)[i] = 0.f;

    auto stage = [&](int c, int buf) {
        int kb = c * 16;
        for (int i = tid; i < 512; i += 256) {      // B: ek/ekv, unconditional (padded, pads=0)
            int kk = i >> 5, d4 = i & 31;
            cpa16(&Bk[buf][kk][d4 * 4], ekB  + (kb + kk) * DD + d4 * 4);
            cpa16(&Bv[buf][kk][d4 * 4], ekvB + (kb + kk) * DD + d4 * 4);
        }
        for (int i = tid; i < 200; i += 256) {      // raw A: 50 rows x 16 k (4x16B per row)
            int p = i >> 2, f4 = i & 3;
            int col = kb + f4 * 4;
            if (col > maxcol) col = maxcol;         // clamp: stays in-row, 16B-aligned
            cpa16(&rawC[buf][p][f4 * 4], cdB + (size_t)p * NN + col);
            cpa16(&rawM[buf][p][f4 * 4], mkB + (size_t)p * NN + col);
        }
    };

    stage(0, 0); CP_COMMIT();
    stage(1, 1); CP_COMMIT();
    for (int c = 0; c < 8; c++) {
        if (c < 7) { CP_WAIT1(); } else { CP_WAIT0(); }
        __syncthreads();
        int cur = c % 3;
        // convert raw -> As (exp); zero k >= valid (covers clamped reads too)
        int kb = c * 16;
        for (int i = tid; i < 800; i += 256) {
            int p = i >> 4, kk = i & 15;
            float e = 0.f;
            if (kb + kk < valid)
                e = to_tf32(__expf(fmaf(-c1, rawC[cur][p][kk], rawM[cur][p][kk])));
            As[p][kk] = e;
        }
        __syncthreads();
        if (c < 6) { stage(c + 2, (c + 2) % 3); CP_COMMIT(); }
#pragma unroll
        for (int k8 = 0; k8 < 16; k8 += 8) {
            unsigned a[2][4];
#pragma unroll
            for (int mt = 0; mt < 2; mt++) {
                int r = wm * 32 + mt * 16 + g;
                a[mt][0] = __float_as_uint(As[r    ][k8 + tg    ]);
                a[mt][1] = __float_as_uint(As[r + 8][k8 + tg    ]);
                a[mt][2] = __float_as_uint(As[r    ][k8 + tg + 4]);
                a[mt][3] = __float_as_uint(As[r + 8][k8 + tg + 4]);
            }
#pragma unroll
            for (int nt = 0; nt < 4; nt++) {
                int d = wn * 32 + nt * 8 + g;
                unsigned bv0 = __float_as_uint(Bv[cur][k8 + tg    ][d]);
                unsigned bv1 = __float_as_uint(Bv[cur][k8 + tg + 4][d]);
                unsigned bk0 = __float_as_uint(Bk[cur][k8 + tg    ][d]);
                unsigned bk1 = __float_as_uint(Bk[cur][k8 + tg + 4][d]);
#pragma unroll
                for (int mt = 0; mt < 2; mt++) {
                    mma_tf32(accN[mt][nt], a[mt], bv0, bv1);
                    mma_tf32(accD[mt][nt], a[mt], bk0, bk1);
                }
            }
        }
        __syncthreads();   // As reused next chunk
    }
#pragma unroll
    for (int mt = 0; mt < 2; mt++) {
        int r = wm * 32 + mt * 16 + g;
#pragma unroll
        for (int nt = 0; nt < 4; nt++) {
            int d = wn * 32 + nt * 8 + tg * 2;
            if (r < 50) {
                size_t o = (size_t)s * RD + ((size_t)b * PP + ph * 50 + r) * DD + d;
                *(float2*)&g_pnum[o] = make_float2(accN[mt][nt][0], accN[mt][nt][1]);
                *(float2*)&g_pden[o] = make_float2(accD[mt][nt][0], accD[mt][nt][1]);
            }
            if (r + 8 < 50) {
                size_t o = (size_t)s * RD + ((size_t)b * PP + ph * 50 + r + 8) * DD + d;
                *(float2*)&g_pnum[o] = make_float2(accN[mt][nt][2], accN[mt][nt][3]);
                *(float2*)&g_pden[o] = make_float2(accD[mt][nt][2], accD[mt][nt][3]);
            }
        }
    }
}

// -------- kernel 4: q = x1@WqfT + x2@WqlT -> g_aft (q only) --------
__global__ __launch_bounds__(256) void q_gemm(const float* __restrict__ x1, const float* __restrict__ x2) {
    int d0 = blockIdx.x * 32;
    int r0 = blockIdx.y * 64;
    int tid = threadIdx.x;
    int rg = tid >> 3, cg = tid & 7;
    __shared__ float x1s[64][17];
    __shared__ float x2s[64][17];
    __shared__ float wfs[16][32];
    __shared__ float wls[16][32];
    float acc[2][4] = {};
    for (int k0 = 0; k0 < 128; k0 += 16) {
        for (int i = tid; i < 1024; i += 256) {
            int r = i >> 4, kk = i & 15;
            size_t g = (size_t)(r0 + r) * DD + k0 + kk;
            x1s[r][kk] = x1[g];
            x2s[r][kk] = x2[g];
        }
        for (int i = tid; i < 512; i += 256) {
            int kk = i >> 5, c = i & 31;
            wfs[kk][c] = g_WqfT[(k0 + kk) * DD + d0 + c];
            wls[kk][c] = g_WqlT[(k0 + kk) * DD + d0 + c];
        }
        __syncthreads();
#pragma unroll
        for (int kk = 0; kk < 16; kk++) {
            float a[2], b2[2];
#pragma unroll
            for (int j = 0; j < 2; j++) { a[j] = x1s[rg * 2 + j][kk]; b2[j] = x2s[rg * 2 + j][kk]; }
            float4 wf4 = *(const float4*)&wfs[kk][cg * 4];
            float4 wl4 = *(const float4*)&wls[kk][cg * 4];
#pragma unroll
            for (int j = 0; j < 2; j++) {
                acc[j][0] += a[j] * wf4.x + b2[j] * wl4.x;
                acc[j][1] += a[j] * wf4.y + b2[j] * wl4.y;
                acc[j][2] += a[j] * wf4.z + b2[j] * wl4.z;
                acc[j][3] += a[j] * wf4.w + b2[j] * wl4.w;
            }
        }
        __syncthreads();
    }
#pragma unroll
    for (int j = 0; j < 2; j++) {
        size_t o = (size_t)(r0 + rg * 2 + j) * DD + d0 + cg * 4;
        *(float4*)&g_aft[o] = make_float4(acc[j][0], acc[j][1], acc[j][2], acc[j][3]);
    }
}

// -------- kernel 5: combine -> aft = tf32(sigmoid(q) * num / den) --------
__global__ __launch_bounds__(256) void combine() {
    size_t i = (size_t)blockIdx.x * 256 + threadIdx.x;   // 0..102399
    size_t o = i * 4;
    float4 q4 = *(const float4*)&g_aft[o];
    float4 ns = make_float4(0.f, 0.f, 0.f, 0.f);
    float4 ds = make_float4(0.f, 0.f, 0.f, 0.f);
#pragma unroll
    for (int s = 0; s < SPLIT; s++) {
        float4 n4 = *(const float4*)&g_pnum[(size_t)s * RD + o];
        float4 d4 = *(const float4*)&g_pden[(size_t)s * RD + o];
        ns.x += n4.x; ns.y += n4.y; ns.z += n4.z; ns.w += n4.w;
        ds.x += d4.x; ds.y += d4.y; ds.z += d4.z; ds.w += d4.w;
    }
    float4 r;
    r.x = to_tf32(ns.x / ds.x / (1.0f + __expf(-q4.x)));
    r.y = to_tf32(ns.y / ds.y / (1.0f + __expf(-q4.y)));
    r.z = to_tf32(ns.z / ds.z / (1.0f + __expf(-q4.z)));
    r.w = to_tf32(ns.w / ds.w / (1.0f + __expf(-q4.w)));
    *(float4*)&g_aft[o] = r;
}

// -------- kernel 6: score via tf32 MMA; epilogue writes exp(logit-10) --------
__global__ __launch_bounds__(256) void score_mma(const float* __restrict__ enc,
                                                 const float* __restrict__ cur_dist,
                                                 const float* __restrict__ mask,
                                                 const float* __restrict__ log_scale,
                                                 const float* __restrict__ dist_alpha,
                                                 float* __restrict__ out) {
    int n0 = blockIdx.x * 64;
    int b  = blockIdx.y;
    int tid = threadIdx.x, lane = tid & 31, wid = tid >> 5;
    int wm = wid >> 2, wn = wid & 3;
    int g = lane >> 2, tg = lane & 3;
    __shared__ float As[3][64][20];    // enc tile [node][k]
    __shared__ float Bs[3][128][20];   // aft tile [p][k]
    float acc[2][4][4] = {};

    auto stage = [&](int c, int buf) {
        int kb = c * 16;
        {
            int nn = tid >> 2, f4 = tid & 3;
            int node = n0 + nn; if (node > 999) node = 999;
            cpa16(&As[buf][nn][f4 * 4], enc + ((size_t)b * NN + node) * DD + kb + f4 * 4);
        }
        for (int i = tid; i < 512; i += 256) {
            int p = i >> 2, f4 = i & 3;
            int pc = p > 99 ? 99 : p;
            cpa16(&Bs[buf][p][f4 * 4], g_aft + ((size_t)b * PP + pc) * DD + kb + f4 * 4);
        }
    };

    stage(0, 0); CP_COMMIT();
    stage(1, 1); CP_COMMIT();
    for (int c = 0; c < 8; c++) {
        if (c < 7) { CP_WAIT1(); } else { CP_WAIT0(); }
        __syncthreads();
        int cur = c % 3;
        if (c < 6) { stage(c + 2, (c + 2) % 3); CP_COMMIT(); }
#pragma unroll
        for (int k8 = 0; k8 < 16; k8 += 8) {
            unsigned a[2][4];
#pragma unroll
            for (int mt = 0; mt < 2; mt++) {
                int r = wm * 32 + mt * 16 + g;
                a[mt][0] = __float_as_uint(to_tf32(As[cur][r    ][k8 + tg    ]));
                a[mt][1] = __float_as_uint(to_tf32(As[cur][r + 8][k8 + tg    ]));
                a[mt][2] = __float_as_uint(to_tf32(As[cur][r    ][k8 + tg + 4]));
                a[mt][3] = __float_as_uint(to_tf32(As[cur][r + 8][k8 + tg + 4]));
            }
#pragma unroll
            for (int nt = 0; nt < 4; nt++) {
                int p = wn * 32 + nt * 8 + g;
                unsigned b0 = __float_as_uint(Bs[cur][p][k8 + tg    ]);
                unsigned b1 = __float_as_uint(Bs[cur][p][k8 + tg + 4]);
#pragma unroll
                for (int mt = 0; mt < 2; mt++) mma_tf32(acc[mt][nt], a[mt], b0, b1);
            }
        }
    }
    float c2 = log_scale[0] * dist_alpha[0];
    const float inv_sqrt_d = 0.08838834764831845f;   // 1/sqrt(128)
#pragma unroll
    for (int mt = 0; mt < 2; mt++) {
#pragma unroll
        for (int nt = 0; nt < 4; nt++) {
#pragma unroll
            for (int e = 0; e < 4; e++) {
                int node = n0 + wm * 32 + mt * 16 + g + (e >> 1) * 8;
                int p    = wn * 32 + nt * 8 + tg * 2 + (e & 1);
                if (node < 1000 && p < 100) {
                    size_t o = ((size_t)b * PP + p) * NN + node;
                    float sc = acc[mt][nt][e] * inv_sqrt_d - c2 * cur_dist[o];
                    out[o] = __expf(10.0f * tanhf(sc) - 10.0f + mask[o]);
                }
            }
        }
    }
}

// -------- kernel 7: normalize rows (out holds exp(logit-10) > 0) --------
__global__ __launch_bounds__(256) void norm_rows(float* __restrict__ out) {
    size_t row = blockIdx.x;
    float* p = out + row * NN;
    int tid = threadIdx.x;
    float v[4];
    int cnt = 0;
    float s = 0.0f;
    for (int i = tid; i < NN; i += 256) { v[cnt] = p[i]; s += v[cnt]; cnt++; }
#pragma unroll
    for (int o = 16; o; o >>= 1) s += __shfl_xor_sync(0xffffffffu, s, o);
    __shared__ float ss[8];
    int w = tid >> 5, l = tid & 31;
    if (l == 0) ss[w] = s;
    __syncthreads();
    float tot = 0.0f;
#pragma unroll
    for (int i = 0; i < 8; i++) tot += ss[i];
    float inv = 1.0f / tot;
    cnt = 0;
    for (int i = tid; i < NN; i += 256) { p[i] = v[cnt] * inv; cnt++; }
}

extern "C" void kernel_launch(void* const* d_in, const int* in_sizes, int n_in,
                              void* d_out, int out_size) {
    const float* enc        = (const float*)d_in[0];   // [B,N,D]
    const float* q1         = (const float*)d_in[1];   // [B,P,D]
    const float* last       = (const float*)d_in[2];   // [B,P,D]
    const float* cur_dist   = (const float*)d_in[3];   // [B,P,N]
    const float* ninf_mask  = (const float*)d_in[4];   // [B,P,N]
    const float* log_scale  = (const float*)d_in[5];   // [1]
    const float* Wq_first   = (const float*)d_in[6];   // [D,D]
    const float* Wq_last    = (const float*)d_in[7];   // [D,D]
    const float* Wk         = (const float*)d_in[8];   // [D,D]
    const float* Wv         = (const float*)d_in[9];   // [D,D]
    const float* dist_alpha = (const float*)d_in[10];  // [1]
    const float* aft_alpha  = (const float*)d_in[11];  // [1]
    float* out = (float*)d_out;                        // [B,P,N]

    transpose_w<<<64, 256>>>(Wk, Wv, Wq_first, Wq_last);
    kv_mma<<<500, 256>>>(enc);
    q_gemm<<<dim3(4, 50), 256>>>(q1, last);
    aft_mma<<<dim3(SPLIT, 2, BB), 256>>>(cur_dist, ninf_mask, log_scale, aft_alpha);
    combine<<<400, 256>>>();
    score_mma<<<dim3(16, 32), 256>>>(enc, cur_dist, ninf_mask, log_scale, dist_alpha, out);
    norm_rows<<<3200, 256>>>(out);
}

// round 16
// speedup vs baseline: 2.3288x; 1.0455x over previous
#include <cuda_runtime.h>
#include <math.h>

// Problem dims
#define BB 32
#define PP 100
#define NN 1000
#define DD 128
#define SPLIT 4
#define SCHUNK 256             // n per split (last split: 232 valid)
#define ROWS (BB*PP)           // 3200
#define RD   ((size_t)ROWS*DD) // 409600
#define NPAD (SPLIT*SCHUNK)    // 1024 padded n per batch

// -------- device scratch (static, allocation-free) --------
__device__ float g_WkT [DD*DD];   // tf32-rounded
__device__ float g_WvT [DD*DD];   // tf32-rounded
__device__ float g_WqfT[DD*DD];
__device__ float g_WqlT[DD*DD];
__device__ float g_ekp [(size_t)BB*NPAD*DD];  // exp(k), tf32, padded (pads stay 0)
__device__ float g_ekvp[(size_t)BB*NPAD*DD];  // exp(k)*v, tf32, padded
__device__ float g_pnum[SPLIT*RD];            // K-split partials
__device__ float g_pden[SPLIT*RD];
__device__ float g_aft [RD];                  // aft (tf32-rounded)

// -------- tf32 mma helpers --------
__device__ __forceinline__ float to_tf32(float x) {
    asm("cvt.rna.tf32.f32 %0, %1;" : "=f"(x) : "f"(x));
    return x;
}
__device__ __forceinline__ void mma_tf32(float c[4], const unsigned a[4], unsigned b0, unsigned b1) {
    asm volatile("mma.sync.aligned.m16n8k8.row.col.f32.tf32.tf32.f32 "
                 "{%0,%1,%2,%3}, {%4,%5,%6,%7}, {%8,%9}, {%0,%1,%2,%3};"
                 : "+f"(c[0]), "+f"(c[1]), "+f"(c[2]), "+f"(c[3])
                 : "r"(a[0]), "r"(a[1]), "r"(a[2]), "r"(a[3]), "r"(b0), "r"(b1));
}

// -------- cp.async helpers --------
__device__ __forceinline__ void cpa16(void* dst_smem, const float* src) {
    unsigned s = (unsigned)__cvta_generic_to_shared(dst_smem);
    asm volatile("cp.async.cg.shared.global [%0], [%1], 16;\n" :: "r"(s), "l"(src));
}
#define CP_COMMIT() asm volatile("cp.async.commit_group;\n" ::: "memory")
#define CP_WAIT0()  asm volatile("cp.async.wait_group 0;\n" ::: "memory")
#define CP_WAIT1()  asm volatile("cp.async.wait_group 1;\n" ::: "memory")

// -------- kernel 1: transpose weights (Wk/Wv pre-rounded to tf32) --------
__global__ void transpose_w(const float* __restrict__ Wk, const float* __restrict__ Wv,
                            const float* __restrict__ Wqf, const float* __restrict__ Wql) {
    int i = blockIdx.x * 256 + threadIdx.x;     // 64*256 = 16384
    int d = i >> 7, k = i & 127;
    int o = k * DD + d;
    g_WkT [o] = to_tf32(Wk[i]);
    g_WvT [o] = to_tf32(Wv[i]);
    g_WqfT[o] = Wqf[i];
    g_WqlT[o] = Wql[i];
}

// -------- kernel 2: k/v projection via tf32 MMA, 3-stage cp.async ring --------
__global__ __launch_bounds__(256) void kv_mma(const float* __restrict__ enc) {
    int r0 = blockIdx.x * 64;          // 500 row tiles
    int tid = threadIdx.x, lane = tid & 31, wid = tid >> 5;
    int wm = wid >> 2, wn = wid & 3;
    int g = lane >> 2, tg = lane & 3;
    __shared__ float As[3][64][20];
    __shared__ float Bk[3][16][136];
    __shared__ float Bv[3][16][136];
    float accK[2][4][4] = {}, accV[2][4][4] = {};

    auto stage = [&](int c, int buf) {
        int kb = c * 16;
        {
            int p = tid >> 2, f4 = tid & 3;
            cpa16(&As[buf][p][f4 * 4], enc + (size_t)(r0 + p) * DD + kb + f4 * 4);
        }
        for (int i = tid; i < 512; i += 256) {
            int kk = i >> 5, d4 = i & 31;
            cpa16(&Bk[buf][kk][d4 * 4], g_WkT + (kb + kk) * DD + d4 * 4);
            cpa16(&Bv[buf][kk][d4 * 4], g_WvT + (kb + kk) * DD + d4 * 4);
        }
    };

    stage(0, 0); CP_COMMIT();
    stage(1, 1); CP_COMMIT();
    for (int c = 0; c < 8; c++) {
        if (c < 7) { CP_WAIT1(); } else { CP_WAIT0(); }
        __syncthreads();
        int cur = c % 3;
        if (c < 6) { stage(c + 2, (c + 2) % 3); CP_COMMIT(); }
#pragma unroll
        for (int k8 = 0; k8 < 16; k8 += 8) {
            unsigned a[2][4];
#pragma unroll
            for (int mt = 0; mt < 2; mt++) {
                int r = wm * 32 + mt * 16 + g;
                a[mt][0] = __float_as_uint(to_tf32(As[cur][r    ][k8 + tg    ]));
                a[mt][1] = __float_as_uint(to_tf32(As[cur][r + 8][k8 + tg    ]));
                a[mt][2] = __float_as_uint(to_tf32(As[cur][r    ][k8 + tg + 4]));
                a[mt][3] = __float_as_uint(to_tf32(As[cur][r + 8][k8 + tg + 4]));
            }
#pragma unroll
            for (int nt = 0; nt < 4; nt++) {
                int d = wn * 32 + nt * 8 + g;
                unsigned bk0 = __float_as_uint(Bk[cur][k8 + tg    ][d]);
                unsigned bk1 = __float_as_uint(Bk[cur][k8 + tg + 4][d]);
                unsigned bv0 = __float_as_uint(Bv[cur][k8 + tg    ][d]);
                unsigned bv1 = __float_as_uint(Bv[cur][k8 + tg + 4][d]);
#pragma unroll
                for (int mt = 0; mt < 2; mt++) {
                    mma_tf32(accK[mt][nt], a[mt], bk0, bk1);
                    mma_tf32(accV[mt][nt], a[mt], bv0, bv1);
                }
            }
        }
    }
    // epilogue: exp + tf32-round into padded layout (n < 1000 <= NPAD)
#pragma unroll
    for (int mt = 0; mt < 2; mt++) {
        int rl = wm * 32 + mt * 16 + g;
        size_t prow[2];
#pragma unroll
        for (int h = 0; h < 2; h++) {
            int gr = r0 + rl + h * 8;
            int bb = gr / 1000;
            int n  = gr - bb * 1000;
            prow[h] = ((size_t)bb * NPAD + n) * DD;
        }
#pragma unroll
        for (int nt = 0; nt < 4; nt++) {
            int d = wn * 32 + nt * 8 + tg * 2;
            float e0 = __expf(accK[mt][nt][0]), e1 = __expf(accK[mt][nt][1]);
            float e2 = __expf(accK[mt][nt][2]), e3 = __expf(accK[mt][nt][3]);
            *(float2*)&g_ekp [prow[0] + d] = make_float2(to_tf32(e0), to_tf32(e1));
            *(float2*)&g_ekvp[prow[0] + d] = make_float2(to_tf32(e0 * accV[mt][nt][0]), to_tf32(e1 * accV[mt][nt][1]));
            *(float2*)&g_ekp [prow[1] + d] = make_float2(to_tf32(e2), to_tf32(e3));
            *(float2*)&g_ekvp[prow[1] + d] = make_float2(to_tf32(e2 * accV[mt][nt][2]), to_tf32(e3 * accV[mt][nt][3]));
        }
    }
}

// -------- kernel 3: AFT num/den via tf32 MMA; 4-way K-split; raw A cp.async-pipelined --------
// grid (SPLIT, 2 p-halves, 32 b). per CTA: M=64(50 p) x N=128 d, K=256 (split 3: 232 valid).
__global__ __launch_bounds__(256) void aft_mma(const float* __restrict__ cur_dist,
                                               const float* __restrict__ mask,
                                               const float* __restrict__ log_scale,
                                               const float* __restrict__ aft_alpha) {
    int s = blockIdx.x, ph = blockIdx.y, b = blockIdx.z;
    int tid = threadIdx.x, lane = tid & 31, wid = tid >> 5;
    int wm = wid >> 2, wn = wid & 3;
    int g = lane >> 2, tg = lane & 3;
    float c1 = log_scale[0] * aft_alpha[0];
    int valid = (s == SPLIT - 1) ? (NN - (SPLIT - 1) * SCHUNK) : SCHUNK;   // 232 or 256
    int maxcol = (valid - 4) & ~3;                                         // 228 or 252
    __shared__ float As[64][20];          // single-buffer, exp'd per chunk
    __shared__ float rawC[3][50][20];     // raw cur_dist tiles
    __shared__ float rawM[3][50][20];     // raw mask tiles
    __shared__ float Bk[3][16][136];
    __shared__ float Bv[3][16][136];
    float accN[2][4][4] = {}, accD[2][4][4] = {};
    const float* ekB  = g_ekp  + ((size_t)b * NPAD + s * SCHUNK) * DD;
    const float* ekvB = g_ekvp + ((size_t)b * NPAD + s * SCHUNK) * DD;
    const float* cdB  = cur_dist + ((size_t)b * PP + ph * 50) * NN + s * SCHUNK;  // 1KB-aligned
    const float* mkB  = mask     + ((size_t)b * PP + ph * 50) * NN + s * SCHUNK;

    for (int i = tid; i < 64 * 20; i += 256) ((float*)As)[i] = 0.f;   // rows 50-63 discarded

    auto stage = [&](int c, int buf) {
        int kb = c * 16;
        for (int i = tid; i < 512; i += 256) {      // B: ek/ekv (padded, pads=0)
            int kk = i >> 5, d4 = i & 31;
            cpa16(&Bk[buf][kk][d4 * 4], ekB  + (kb + kk) * DD + d4 * 4);
            cpa16(&Bv[buf][kk][d4 * 4], ekvB + (kb + kk) * DD + d4 * 4);
        }
        for (int i = tid; i < 200; i += 256) {      // raw A: 50 rows x 16 k
            int p = i >> 2, f4 = i & 3;
            int col = kb + f4 * 4;
            if (col > maxcol) col = maxcol;         // clamp: in-row, 16B-aligned
            cpa16(&rawC[buf][p][f4 * 4], cdB + (size_t)p * NN + col);
            cpa16(&rawM[buf][p][f4 * 4], mkB + (size_t)p * NN + col);
        }
    };

    stage(0, 0); CP_COMMIT();
    stage(1, 1); CP_COMMIT();
    for (int c = 0; c < 16; c++) {
        if (c < 15) { CP_WAIT1(); } else { CP_WAIT0(); }
        __syncthreads();
        int cur = c % 3;
        int kb = c * 16;
        for (int i = tid; i < 800; i += 256) {      // convert raw -> As (exp); zero k>=valid
            int p = i >> 4, kk = i & 15;
            float e = 0.f;
            if (kb + kk < valid)
                e = to_tf32(__expf(fmaf(-c1, rawC[cur][p][kk], rawM[cur][p][kk])));
            As[p][kk] = e;
        }
        __syncthreads();
        if (c < 14) { stage(c + 2, (c + 2) % 3); CP_COMMIT(); }
#pragma unroll
        for (int k8 = 0; k8 < 16; k8 += 8) {
            unsigned a[2][4];
#pragma unroll
            for (int mt = 0; mt < 2; mt++) {
                int r = wm * 32 + mt * 16 + g;
                a[mt][0] = __float_as_uint(As[r    ][k8 + tg    ]);
                a[mt][1] = __float_as_uint(As[r + 8][k8 + tg    ]);
                a[mt][2] = __float_as_uint(As[r    ][k8 + tg + 4]);
                a[mt][3] = __float_as_uint(As[r + 8][k8 + tg + 4]);
            }
#pragma unroll
            for (int nt = 0; nt < 4; nt++) {
                int d = wn * 32 + nt * 8 + g;
                unsigned bv0 = __float_as_uint(Bv[cur][k8 + tg    ][d]);
                unsigned bv1 = __float_as_uint(Bv[cur][k8 + tg + 4][d]);
                unsigned bk0 = __float_as_uint(Bk[cur][k8 + tg    ][d]);
                unsigned bk1 = __float_as_uint(Bk[cur][k8 + tg + 4][d]);
#pragma unroll
                for (int mt = 0; mt < 2; mt++) {
                    mma_tf32(accN[mt][nt], a[mt], bv0, bv1);
                    mma_tf32(accD[mt][nt], a[mt], bk0, bk1);
                }
            }
        }
        __syncthreads();   // As reused next chunk
    }
#pragma unroll
    for (int mt = 0; mt < 2; mt++) {
        int r = wm * 32 + mt * 16 + g;
#pragma unroll
        for (int nt = 0; nt < 4; nt++) {
            int d = wn * 32 + nt * 8 + tg * 2;
            if (r < 50) {
                size_t o = (size_t)s * RD + ((size_t)b * PP + ph * 50 + r) * DD + d;
                *(float2*)&g_pnum[o] = make_float2(accN[mt][nt][0], accN[mt][nt][1]);
                *(float2*)&g_pden[o] = make_float2(accD[mt][nt][0], accD[mt][nt][1]);
            }
            if (r + 8 < 50) {
                size_t o = (size_t)s * RD + ((size_t)b * PP + ph * 50 + r + 8) * DD + d;
                *(float2*)&g_pnum[o] = make_float2(accN[mt][nt][2], accN[mt][nt][3]);
                *(float2*)&g_pden[o] = make_float2(accD[mt][nt][2], accD[mt][nt][3]);
            }
        }
    }
}

// -------- kernel 4: q = x1@WqfT + x2@WqlT; fused combine -> aft = tf32(sigmoid(q)*num/den) --------
__global__ __launch_bounds__(256) void q_combine(const float* __restrict__ x1, const float* __restrict__ x2) {
    int d0 = blockIdx.x * 32;
    int r0 = blockIdx.y * 64;
    int tid = threadIdx.x;
    int rg = tid >> 3, cg = tid & 7;
    __shared__ float x1s[64][17];
    __shared__ float x2s[64][17];
    __shared__ float wfs[16][32];
    __shared__ float wls[16][32];
    float acc[2][4] = {};
    for (int k0 = 0; k0 < 128; k0 += 16) {
        for (int i = tid; i < 1024; i += 256) {
            int r = i >> 4, kk = i & 15;
            size_t g = (size_t)(r0 + r) * DD + k0 + kk;
            x1s[r][kk] = x1[g];
            x2s[r][kk] = x2[g];
        }
        for (int i = tid; i < 512; i += 256) {
            int kk = i >> 5, c = i & 31;
            wfs[kk][c] = g_WqfT[(k0 + kk) * DD + d0 + c];
            wls[kk][c] = g_WqlT[(k0 + kk) * DD + d0 + c];
        }
        __syncthreads();
#pragma unroll
        for (int kk = 0; kk < 16; kk++) {
            float a[2], b2[2];
#pragma unroll
            for (int j = 0; j < 2; j++) { a[j] = x1s[rg * 2 + j][kk]; b2[j] = x2s[rg * 2 + j][kk]; }
            float4 wf4 = *(const float4*)&wfs[kk][cg * 4];
            float4 wl4 = *(const float4*)&wls[kk][cg * 4];
#pragma unroll
            for (int j = 0; j < 2; j++) {
                acc[j][0] += a[j] * wf4.x + b2[j] * wl4.x;
                acc[j][1] += a[j] * wf4.y + b2[j] * wl4.y;
                acc[j][2] += a[j] * wf4.z + b2[j] * wl4.z;
                acc[j][3] += a[j] * wf4.w + b2[j] * wl4.w;
            }
        }
        __syncthreads();
    }
#pragma unroll
    for (int j = 0; j < 2; j++) {
        size_t o = (size_t)(r0 + rg * 2 + j) * DD + d0 + cg * 4;
        float4 ns = make_float4(0.f, 0.f, 0.f, 0.f);
        float4 ds = make_float4(0.f, 0.f, 0.f, 0.f);
#pragma unroll
        for (int s = 0; s < SPLIT; s++) {
            float4 n4 = *(const float4*)&g_pnum[(size_t)s * RD + o];
            float4 d4 = *(const float4*)&g_pden[(size_t)s * RD + o];
            ns.x += n4.x; ns.y += n4.y; ns.z += n4.z; ns.w += n4.w;
            ds.x += d4.x; ds.y += d4.y; ds.z += d4.z; ds.w += d4.w;
        }
        float4 r;
        r.x = to_tf32(ns.x / ds.x / (1.0f + __expf(-acc[j][0])));
        r.y = to_tf32(ns.y / ds.y / (1.0f + __expf(-acc[j][1])));
        r.z = to_tf32(ns.z / ds.z / (1.0f + __expf(-acc[j][2])));
        r.w = to_tf32(ns.w / ds.w / (1.0f + __expf(-acc[j][3])));
        *(float4*)&g_aft[o] = r;
    }
}

// -------- kernel 5: score via tf32 MMA; epilogue writes exp(logit-10) --------
__global__ __launch_bounds__(256) void score_mma(const float* __restrict__ enc,
                                                 const float* __restrict__ cur_dist,
                                                 const float* __restrict__ mask,
                                                 const float* __restrict__ log_scale,
                                                 const float* __restrict__ dist_alpha,
                                                 float* __restrict__ out) {
    int n0 = blockIdx.x * 64;
    int b  = blockIdx.y;
    int tid = threadIdx.x, lane = tid & 31, wid = tid >> 5;
    int wm = wid >> 2, wn = wid & 3;
    int g = lane >> 2, tg = lane & 3;
    __shared__ float As[3][64][20];    // enc tile [node][k]
    __shared__ float Bs[3][128][20];   // aft tile [p][k]
    float acc[2][4][4] = {};

    auto stage = [&](int c, int buf) {
        int kb = c * 16;
        {
            int nn = tid >> 2, f4 = tid & 3;
            int node = n0 + nn; if (node > 999) node = 999;
            cpa16(&As[buf][nn][f4 * 4], enc + ((size_t)b * NN + node) * DD + kb + f4 * 4);
        }
        for (int i = tid; i < 512; i += 256) {
            int p = i >> 2, f4 = i & 3;
            int pc = p > 99 ? 99 : p;
            cpa16(&Bs[buf][p][f4 * 4], g_aft + ((size_t)b * PP + pc) * DD + kb + f4 * 4);
        }
    };

    stage(0, 0); CP_COMMIT();
    stage(1, 1); CP_COMMIT();
    for (int c = 0; c < 8; c++) {
        if (c < 7) { CP_WAIT1(); } else { CP_WAIT0(); }
        __syncthreads();
        int cur = c % 3;
        if (c < 6) { stage(c + 2, (c + 2) % 3); CP_COMMIT(); }
#pragma unroll
        for (int k8 = 0; k8 < 16; k8 += 8) {
            unsigned a[2][4];
#pragma unroll
            for (int mt = 0; mt < 2; mt++) {
                int r = wm * 32 + mt * 16 + g;
                a[mt][0] = __float_as_uint(to_tf32(As[cur][r    ][k8 + tg    ]));
                a[mt][1] = __float_as_uint(to_tf32(As[cur][r + 8][k8 + tg    ]));
                a[mt][2] = __float_as_uint(to_tf32(As[cur][r    ][k8 + tg + 4]));
                a[mt][3] = __float_as_uint(to_tf32(As[cur][r + 8][k8 + tg + 4]));
            }
#pragma unroll
            for (int nt = 0; nt < 4; nt++) {
                int p = wn * 32 + nt * 8 + g;
                unsigned b0 = __float_as_uint(Bs[cur][p][k8 + tg    ]);
                unsigned b1 = __float_as_uint(Bs[cur][p][k8 + tg + 4]);
#pragma unroll
                for (int mt = 0; mt < 2; mt++) mma_tf32(acc[mt][nt], a[mt], b0, b1);
            }
        }
    }
    float c2 = log_scale[0] * dist_alpha[0];
    const float inv_sqrt_d = 0.08838834764831845f;   // 1/sqrt(128)
#pragma unroll
    for (int mt = 0; mt < 2; mt++) {
#pragma unroll
        for (int nt = 0; nt < 4; nt++) {
#pragma unroll
            for (int e = 0; e < 4; e++) {
                int node = n0 + wm * 32 + mt * 16 + g + (e >> 1) * 8;
                int p    = wn * 32 + nt * 8 + tg * 2 + (e & 1);
                if (node < 1000 && p < 100) {
                    size_t o = ((size_t)b * PP + p) * NN + node;
                    float sc = acc[mt][nt][e] * inv_sqrt_d - c2 * cur_dist[o];
                    out[o] = __expf(10.0f * tanhf(sc) - 10.0f + mask[o]);
                }
            }
        }
    }
}

// -------- kernel 6: normalize rows (out holds exp(logit-10) > 0), float4 --------
__global__ __launch_bounds__(256) void norm_rows(float* __restrict__ out) {
    size_t row = blockIdx.x;
    float4* p = (float4*)(out + row * NN);   // 1000 floats = 250 float4, 16B-aligned rows
    int tid = threadIdx.x;
    float4 v = make_float4(0.f, 0.f, 0.f, 0.f);
    float s = 0.f;
    if (tid < 250) { v = p[tid]; s = (v.x + v.y) + (v.z + v.w); }
#pragma unroll
    for (int o = 16; o; o >>= 1) s += __shfl_xor_sync(0xffffffffu, s, o);
    __shared__ float ss[8];
    int w = tid >> 5, l = tid & 31;
    if (l == 0) ss[w] = s;
    __syncthreads();
    float tot = 0.f;
#pragma unroll
    for (int i = 0; i < 8; i++) tot += ss[i];
    float inv = 1.0f / tot;
    if (tid < 250) {
        v.x *= inv; v.y *= inv; v.z *= inv; v.w *= inv;
        p[tid] = v;
    }
}

extern "C" void kernel_launch(void* const* d_in, const int* in_sizes, int n_in,
                              void* d_out, int out_size) {
    const float* enc        = (const float*)d_in[0];   // [B,N,D]
    const float* q1         = (const float*)d_in[1];   // [B,P,D]
    const float* last       = (const float*)d_in[2];   // [B,P,D]
    const float* cur_dist   = (const float*)d_in[3];   // [B,P,N]
    const float* ninf_mask  = (const float*)d_in[4];   // [B,P,N]
    const float* log_scale  = (const float*)d_in[5];   // [1]
    const float* Wq_first   = (const float*)d_in[6];   // [D,D]
    const float* Wq_last    = (const float*)d_in[7];   // [D,D]
    const float* Wk         = (const float*)d_in[8];   // [D,D]
    const float* Wv         = (const float*)d_in[9];   // [D,D]
    const float* dist_alpha = (const float*)d_in[10];  // [1]
    const float* aft_alpha  = (const float*)d_in[11];  // [1]
    float* out = (float*)d_out;                        // [B,P,N]

    transpose_w<<<64, 256>>>(Wk, Wv, Wq_first, Wq_last);
    kv_mma<<<500, 256>>>(enc);
    aft_mma<<<dim3(SPLIT, 2, BB), 256>>>(cur_dist, ninf_mask, log_scale, aft_alpha);
    q_combine<<<dim3(4, 50), 256>>>(q1, last);
    score_mma<<<dim3(16, 32), 256>>>(enc, cur_dist, ninf_mask, log_scale, dist_alpha, out);
    norm_rows<<<3200, 256>>>(out);
}

// round 17
// speedup vs baseline: 2.7518x; 1.1816x over previous
#include <cuda_runtime.h>
#include <math.h>

// Problem dims
#define BB 32
#define PP 100
#define NN 1000
#define DD 128
#define SPLIT 4
#define SCHUNK 256             // n per split (last split: 232 valid)
#define ROWS (BB*PP)           // 3200
#define RD   ((size_t)ROWS*DD) // 409600
#define NPAD (SPLIT*SCHUNK)    // 1024 padded n per batch

// -------- device scratch (static, allocation-free) --------
__device__ float g_WkT [DD*DD];   // tf32-rounded
__device__ float g_WvT [DD*DD];   // tf32-rounded
__device__ float g_WqfT[DD*DD];
__device__ float g_WqlT[DD*DD];
__device__ float g_ekp [(size_t)BB*NPAD*DD];  // exp(k), tf32, padded (pads stay 0)
__device__ float g_ekvp[(size_t)BB*NPAD*DD];  // exp(k)*v, tf32, padded
__device__ float g_pnum[SPLIT*RD];            // K-split partials
__device__ float g_pden[SPLIT*RD];
__device__ float g_aft [RD];                  // aft (tf32-rounded)

// -------- tf32 mma helpers --------
__device__ __forceinline__ float to_tf32(float x) {
    asm("cvt.rna.tf32.f32 %0, %1;" : "=f"(x) : "f"(x));
    return x;
}
__device__ __forceinline__ void mma_tf32(float c[4], const unsigned a[4], unsigned b0, unsigned b1) {
    asm volatile("mma.sync.aligned.m16n8k8.row.col.f32.tf32.tf32.f32 "
                 "{%0,%1,%2,%3}, {%4,%5,%6,%7}, {%8,%9}, {%0,%1,%2,%3};"
                 : "+f"(c[0]), "+f"(c[1]), "+f"(c[2]), "+f"(c[3])
                 : "r"(a[0]), "r"(a[1]), "r"(a[2]), "r"(a[3]), "r"(b0), "r"(b1));
}

// -------- cp.async helpers --------
__device__ __forceinline__ void cpa16(void* dst_smem, const float* src) {
    unsigned s = (unsigned)__cvta_generic_to_shared(dst_smem);
    asm volatile("cp.async.cg.shared.global [%0], [%1], 16;\n" :: "r"(s), "l"(src));
}
#define CP_COMMIT() asm volatile("cp.async.commit_group;\n" ::: "memory")
#define CP_WAIT0()  asm volatile("cp.async.wait_group 0;\n" ::: "memory")
#define CP_WAIT1()  asm volatile("cp.async.wait_group 1;\n" ::: "memory")

// -------- kernel 1: transpose weights (Wk/Wv pre-rounded to tf32) --------
__global__ void transpose_w(const float* __restrict__ Wk, const float* __restrict__ Wv,
                            const float* __restrict__ Wqf, const float* __restrict__ Wql) {
    int i = blockIdx.x * 256 + threadIdx.x;     // 64*256 = 16384
    int d = i >> 7, k = i & 127;
    int o = k * DD + d;
    g_WkT [o] = to_tf32(Wk[i]);
    g_WvT [o] = to_tf32(Wv[i]);
    g_WqfT[o] = Wqf[i];
    g_WqlT[o] = Wql[i];
}

// -------- kernel 2: k/v projection via tf32 MMA, 3-stage cp.async ring --------
__global__ __launch_bounds__(256) void kv_mma(const float* __restrict__ enc) {
    int r0 = blockIdx.x * 64;          // 500 row tiles
    int tid = threadIdx.x, lane = tid & 31, wid = tid >> 5;
    int wm = wid >> 2, wn = wid & 3;
    int g = lane >> 2, tg = lane & 3;
    __shared__ float As[3][64][20];
    __shared__ float Bk[3][16][136];
    __shared__ float Bv[3][16][136];
    float accK[2][4][4] = {}, accV[2][4][4] = {};

    auto stage = [&](int c, int buf) {
        int kb = c * 16;
        {
            int p = tid >> 2, f4 = tid & 3;
            cpa16(&As[buf][p][f4 * 4], enc + (size_t)(r0 + p) * DD + kb + f4 * 4);
        }
        for (int i = tid; i < 512; i += 256) {
            int kk = i >> 5, d4 = i & 31;
            cpa16(&Bk[buf][kk][d4 * 4], g_WkT + (kb + kk) * DD + d4 * 4);
            cpa16(&Bv[buf][kk][d4 * 4], g_WvT + (kb + kk) * DD + d4 * 4);
        }
    };

    stage(0, 0); CP_COMMIT();
    stage(1, 1); CP_COMMIT();
    for (int c = 0; c < 8; c++) {
        if (c < 7) { CP_WAIT1(); } else { CP_WAIT0(); }
        __syncthreads();
        int cur = c % 3;
        if (c < 6) { stage(c + 2, (c + 2) % 3); CP_COMMIT(); }
#pragma unroll
        for (int k8 = 0; k8 < 16; k8 += 8) {
            unsigned a[2][4];
#pragma unroll
            for (int mt = 0; mt < 2; mt++) {
                int r = wm * 32 + mt * 16 + g;
                a[mt][0] = __float_as_uint(to_tf32(As[cur][r    ][k8 + tg    ]));
                a[mt][1] = __float_as_uint(to_tf32(As[cur][r + 8][k8 + tg    ]));
                a[mt][2] = __float_as_uint(to_tf32(As[cur][r    ][k8 + tg + 4]));
                a[mt][3] = __float_as_uint(to_tf32(As[cur][r + 8][k8 + tg + 4]));
            }
#pragma unroll
            for (int nt = 0; nt < 4; nt++) {
                int d = wn * 32 + nt * 8 + g;
                unsigned bk0 = __float_as_uint(Bk[cur][k8 + tg    ][d]);
                unsigned bk1 = __float_as_uint(Bk[cur][k8 + tg + 4][d]);
                unsigned bv0 = __float_as_uint(Bv[cur][k8 + tg    ][d]);
                unsigned bv1 = __float_as_uint(Bv[cur][k8 + tg + 4][d]);
#pragma unroll
                for (int mt = 0; mt < 2; mt++) {
                    mma_tf32(accK[mt][nt], a[mt], bk0, bk1);
                    mma_tf32(accV[mt][nt], a[mt], bv0, bv1);
                }
            }
        }
    }
    // epilogue: exp + tf32-round into padded layout
#pragma unroll
    for (int mt = 0; mt < 2; mt++) {
        int rl = wm * 32 + mt * 16 + g;
        size_t prow[2];
#pragma unroll
        for (int h = 0; h < 2; h++) {
            int gr = r0 + rl + h * 8;
            int bb = gr / 1000;
            int n  = gr - bb * 1000;
            prow[h] = ((size_t)bb * NPAD + n) * DD;
        }
#pragma unroll
        for (int nt = 0; nt < 4; nt++) {
            int d = wn * 32 + nt * 8 + tg * 2;
            float e0 = __expf(accK[mt][nt][0]), e1 = __expf(accK[mt][nt][1]);
            float e2 = __expf(accK[mt][nt][2]), e3 = __expf(accK[mt][nt][3]);
            *(float2*)&g_ekp [prow[0] + d] = make_float2(to_tf32(e0), to_tf32(e1));
            *(float2*)&g_ekvp[prow[0] + d] = make_float2(to_tf32(e0 * accV[mt][nt][0]), to_tf32(e1 * accV[mt][nt][1]));
            *(float2*)&g_ekp [prow[1] + d] = make_float2(to_tf32(e2), to_tf32(e3));
            *(float2*)&g_ekvp[prow[1] + d] = make_float2(to_tf32(e2 * accV[mt][nt][2]), to_tf32(e3 * accV[mt][nt][3]));
        }
    }
}

// -------- kernel 3: AFT num/den via tf32 MMA; 4-way K-split; raw A cp.async-pipelined --------
__global__ __launch_bounds__(256) void aft_mma(const float* __restrict__ cur_dist,
                                               const float* __restrict__ mask,
                                               const float* __restrict__ log_scale,
                                               const float* __restrict__ aft_alpha) {
    int s = blockIdx.x, ph = blockIdx.y, b = blockIdx.z;
    int tid = threadIdx.x, lane = tid & 31, wid = tid >> 5;
    int wm = wid >> 2, wn = wid & 3;
    int g = lane >> 2, tg = lane & 3;
    float c1 = log_scale[0] * aft_alpha[0];
    int valid = (s == SPLIT - 1) ? (NN - (SPLIT - 1) * SCHUNK) : SCHUNK;   // 232 or 256
    int maxcol = (valid - 4) & ~3;                                         // 228 or 252
    __shared__ float As[64][20];          // single-buffer, exp'd per chunk
    __shared__ float rawC[3][50][20];     // raw cur_dist tiles
    __shared__ float rawM[3][50][20];     // raw mask tiles
    __shared__ float Bk[3][16][136];
    __shared__ float Bv[3][16][136];
    float accN[2][4][4] = {}, accD[2][4][4] = {};
    const float* ekB  = g_ekp  + ((size_t)b * NPAD + s * SCHUNK) * DD;
    const float* ekvB = g_ekvp + ((size_t)b * NPAD + s * SCHUNK) * DD;
    const float* cdB  = cur_dist + ((size_t)b * PP + ph * 50) * NN + s * SCHUNK;
    const float* mkB  = mask     + ((size_t)b * PP + ph * 50) * NN + s * SCHUNK;

    for (int i = tid; i < 64 * 20; i += 256) ((float*)As)[i] = 0.f;

    auto stage = [&](int c, int buf) {
        int kb = c * 16;
        for (int i = tid; i < 512; i += 256) {
            int kk = i >> 5, d4 = i & 31;
            cpa16(&Bk[buf][kk][d4 * 4], ekB  + (kb + kk) * DD + d4 * 4);
            cpa16(&Bv[buf][kk][d4 * 4], ekvB + (kb + kk) * DD + d4 * 4);
        }
        for (int i = tid; i < 200; i += 256) {
            int p = i >> 2, f4 = i & 3;
            int col = kb + f4 * 4;
            if (col > maxcol) col = maxcol;
            cpa16(&rawC[buf][p][f4 * 4], cdB + (size_t)p * NN + col);
            cpa16(&rawM[buf][p][f4 * 4], mkB + (size_t)p * NN + col);
        }
    };

    stage(0, 0); CP_COMMIT();
    stage(1, 1); CP_COMMIT();
    for (int c = 0; c < 16; c++) {
        if (c < 15) { CP_WAIT1(); } else { CP_WAIT0(); }
        __syncthreads();
        int cur = c % 3;
        int kb = c * 16;
        for (int i = tid; i < 800; i += 256) {
            int p = i >> 4, kk = i & 15;
            float e = 0.f;
            if (kb + kk < valid)
                e = to_tf32(__expf(fmaf(-c1, rawC[cur][p][kk], rawM[cur][p][kk])));
            As[p][kk] = e;
        }
        __syncthreads();
        if (c < 14) { stage(c + 2, (c + 2) % 3); CP_COMMIT(); }
#pragma unroll
        for (int k8 = 0; k8 < 16; k8 += 8) {
            unsigned a[2][4];
#pragma unroll
            for (int mt = 0; mt < 2; mt++) {
                int r = wm * 32 + mt * 16 + g;
                a[mt][0] = __float_as_uint(As[r    ][k8 + tg    ]);
                a[mt][1] = __float_as_uint(As[r + 8][k8 + tg    ]);
                a[mt][2] = __float_as_uint(As[r    ][k8 + tg + 4]);
                a[mt][3] = __float_as_uint(As[r + 8][k8 + tg + 4]);
            }
#pragma unroll
            for (int nt = 0; nt < 4; nt++) {
                int d = wn * 32 + nt * 8 + g;
                unsigned bv0 = __float_as_uint(Bv[cur][k8 + tg    ][d]);
                unsigned bv1 = __float_as_uint(Bv[cur][k8 + tg + 4][d]);
                unsigned bk0 = __float_as_uint(Bk[cur][k8 + tg    ][d]);
                unsigned bk1 = __float_as_uint(Bk[cur][k8 + tg + 4][d]);
#pragma unroll
                for (int mt = 0; mt < 2; mt++) {
                    mma_tf32(accN[mt][nt], a[mt], bv0, bv1);
                    mma_tf32(accD[mt][nt], a[mt], bk0, bk1);
                }
            }
        }
        __syncthreads();
    }
#pragma unroll
    for (int mt = 0; mt < 2; mt++) {
        int r = wm * 32 + mt * 16 + g;
#pragma unroll
        for (int nt = 0; nt < 4; nt++) {
            int d = wn * 32 + nt * 8 + tg * 2;
            if (r < 50) {
                size_t o = (size_t)s * RD + ((size_t)b * PP + ph * 50 + r) * DD + d;
                *(float2*)&g_pnum[o] = make_float2(accN[mt][nt][0], accN[mt][nt][1]);
                *(float2*)&g_pden[o] = make_float2(accD[mt][nt][0], accD[mt][nt][1]);
            }
            if (r + 8 < 50) {
                size_t o = (size_t)s * RD + ((size_t)b * PP + ph * 50 + r + 8) * DD + d;
                *(float2*)&g_pnum[o] = make_float2(accN[mt][nt][2], accN[mt][nt][3]);
                *(float2*)&g_pden[o] = make_float2(accD[mt][nt][2], accD[mt][nt][3]);
            }
        }
    }
}

// -------- kernel 4: q GEMM (cp.async 3-stage) + fused combine epilogue --------
__global__ __launch_bounds__(256) void q_combine(const float* __restrict__ x1, const float* __restrict__ x2) {
    int d0 = blockIdx.x * 32;
    int r0 = blockIdx.y * 64;
    int tid = threadIdx.x;
    int rg = tid >> 3, cg = tid & 7;
    __shared__ float x1s[3][64][20];
    __shared__ float x2s[3][64][20];
    __shared__ float wfs[3][16][36];
    __shared__ float wls[3][16][36];
    float acc[2][4] = {};

    auto stage = [&](int c, int buf) {
        int kb = c * 16;
        {   // x1/x2: 64 rows x 16 k, 4x16B per row
            int p = tid >> 2, f4 = tid & 3;
            cpa16(&x1s[buf][p][f4 * 4], x1 + (size_t)(r0 + p) * DD + kb + f4 * 4);
            cpa16(&x2s[buf][p][f4 * 4], x2 + (size_t)(r0 + p) * DD + kb + f4 * 4);
        }
        {   // weights: 16 k x 32 d each; threads 0-127 -> wfs, 128-255 -> wls
            int i = tid & 127;
            int kk = i >> 3, c4 = i & 7;
            if (tid < 128) cpa16(&wfs[buf][kk][c4 * 4], g_WqfT + (kb + kk) * DD + d0 + c4 * 4);
            else           cpa16(&wls[buf][kk][c4 * 4], g_WqlT + (kb + kk) * DD + d0 + c4 * 4);
        }
    };

    stage(0, 0); CP_COMMIT();
    stage(1, 1); CP_COMMIT();
    for (int c = 0; c < 8; c++) {
        if (c < 7) { CP_WAIT1(); } else { CP_WAIT0(); }
        __syncthreads();
        int cur = c % 3;
        if (c < 6) { stage(c + 2, (c + 2) % 3); CP_COMMIT(); }
#pragma unroll
        for (int kk = 0; kk < 16; kk++) {
            float a[2], b2[2];
#pragma unroll
            for (int j = 0; j < 2; j++) { a[j] = x1s[cur][rg * 2 + j][kk]; b2[j] = x2s[cur][rg * 2 + j][kk]; }
            float4 wf4 = *(const float4*)&wfs[cur][kk][cg * 4];
            float4 wl4 = *(const float4*)&wls[cur][kk][cg * 4];
#pragma unroll
            for (int j = 0; j < 2; j++) {
                acc[j][0] += a[j] * wf4.x + b2[j] * wl4.x;
                acc[j][1] += a[j] * wf4.y + b2[j] * wl4.y;
                acc[j][2] += a[j] * wf4.z + b2[j] * wl4.z;
                acc[j][3] += a[j] * wf4.w + b2[j] * wl4.w;
            }
        }
    }
#pragma unroll
    for (int j = 0; j < 2; j++) {
        size_t o = (size_t)(r0 + rg * 2 + j) * DD + d0 + cg * 4;
        float4 ns = make_float4(0.f, 0.f, 0.f, 0.f);
        float4 ds = make_float4(0.f, 0.f, 0.f, 0.f);
#pragma unroll
        for (int s = 0; s < SPLIT; s++) {
            float4 n4 = *(const float4*)&g_pnum[(size_t)s * RD + o];
            float4 d4 = *(const float4*)&g_pden[(size_t)s * RD + o];
            ns.x += n4.x; ns.y += n4.y; ns.z += n4.z; ns.w += n4.w;
            ds.x += d4.x; ds.y += d4.y; ds.z += d4.z; ds.w += d4.w;
        }
        float4 r;
        r.x = to_tf32(ns.x / ds.x / (1.0f + __expf(-acc[j][0])));
        r.y = to_tf32(ns.y / ds.y / (1.0f + __expf(-acc[j][1])));
        r.z = to_tf32(ns.z / ds.z / (1.0f + __expf(-acc[j][2])));
        r.w = to_tf32(ns.w / ds.w / (1.0f + __expf(-acc[j][3])));
        *(float4*)&g_aft[o] = r;
    }
}

// -------- kernel 5: score via tf32 MMA; dist/mask prefetched to smem; epilogue exp(logit-10) --------
__global__ __launch_bounds__(256) void score_mma(const float* __restrict__ enc,
                                                 const float* __restrict__ cur_dist,
                                                 const float* __restrict__ mask,
                                                 const float* __restrict__ log_scale,
                                                 const float* __restrict__ dist_alpha,
                                                 float* __restrict__ out) {
    int n0 = blockIdx.x * 64;
    int b  = blockIdx.y;
    int tid = threadIdx.x, lane = tid & 31, wid = tid >> 5;
    int wm = wid >> 2, wn = wid & 3;
    int g = lane >> 2, tg = lane & 3;
    __shared__ float As[3][64][20];    // enc tile [node][k]
    __shared__ float Bs[3][128][20];   // aft tile [p][k]
    __shared__ float distC[100][68];   // cur_dist [p][node-n0]
    __shared__ float distM[100][68];   // mask     [p][node-n0]
    float acc[2][4][4] = {};

    auto stage = [&](int c, int buf) {
        int kb = c * 16;
        {
            int nn = tid >> 2, f4 = tid & 3;
            int node = n0 + nn; if (node > 999) node = 999;
            cpa16(&As[buf][nn][f4 * 4], enc + ((size_t)b * NN + node) * DD + kb + f4 * 4);
        }
        for (int i = tid; i < 512; i += 256) {
            int p = i >> 2, f4 = i & 3;
            int pc = p > 99 ? 99 : p;
            cpa16(&Bs[buf][p][f4 * 4], g_aft + ((size_t)b * PP + pc) * DD + kb + f4 * 4);
        }
    };

    stage(0, 0); CP_COMMIT();
    stage(1, 1); CP_COMMIT();
    // prefetch dist/mask tiles (own group; complete by c=1's wait, used at epilogue).
    // Reads may run ≤60 floats past the row end (tail tile) — stays inside the mapped
    // allocation region; those smem slots are never read (node<1000 guard).
    for (int i = tid; i < 1600; i += 256) {
        int p = i >> 4, f4 = i & 15;
        size_t gsrc = ((size_t)b * PP + p) * NN + n0 + f4 * 4;
        cpa16(&distC[p][f4 * 4], cur_dist + gsrc);
        cpa16(&distM[p][f4 * 4], mask + gsrc);
    }
    CP_COMMIT();
    for (int c = 0; c < 8; c++) {
        if (c < 7) { CP_WAIT1(); } else { CP_WAIT0(); }
        __syncthreads();
        int cur = c % 3;
        if (c < 6) { stage(c + 2, (c + 2) % 3); CP_COMMIT(); }
#pragma unroll
        for (int k8 = 0; k8 < 16; k8 += 8) {
            unsigned a[2][4];
#pragma unroll
            for (int mt = 0; mt < 2; mt++) {
                int r = wm * 32 + mt * 16 + g;
                a[mt][0] = __float_as_uint(to_tf32(As[cur][r    ][k8 + tg    ]));
                a[mt][1] = __float_as_uint(to_tf32(As[cur][r + 8][k8 + tg    ]));
                a[mt][2] = __float_as_uint(to_tf32(As[cur][r    ][k8 + tg + 4]));
                a[mt][3] = __float_as_uint(to_tf32(As[cur][r + 8][k8 + tg + 4]));
            }
#pragma unroll
            for (int nt = 0; nt < 4; nt++) {
                int p = wn * 32 + nt * 8 + g;
                unsigned b0 = __float_as_uint(Bs[cur][p][k8 + tg    ]);
                unsigned b1 = __float_as_uint(Bs[cur][p][k8 + tg + 4]);
#pragma unroll
                for (int mt = 0; mt < 2; mt++) mma_tf32(acc[mt][nt], a[mt], b0, b1);
            }
        }
    }
    float c2 = log_scale[0] * dist_alpha[0];
    const float inv_sqrt_d = 0.08838834764831845f;   // 1/sqrt(128)
#pragma unroll
    for (int mt = 0; mt < 2; mt++) {
#pragma unroll
        for (int nt = 0; nt < 4; nt++) {
#pragma unroll
            for (int e = 0; e < 4; e++) {
                int node = n0 + wm * 32 + mt * 16 + g + (e >> 1) * 8;
                int p    = wn * 32 + nt * 8 + tg * 2 + (e & 1);
                if (node < 1000 && p < 100) {
                    int no = node - n0;
                    float sc = acc[mt][nt][e] * inv_sqrt_d - c2 * distC[p][no];
                    out[((size_t)b * PP + p) * NN + node] =
                        __expf(10.0f * tanhf(sc) - 10.0f + distM[p][no]);
                }
            }
        }
    }
}

// -------- kernel 6: normalize rows (out holds exp(logit-10) > 0), float4 --------
__global__ __launch_bounds__(256) void norm_rows(float* __restrict__ out) {
    size_t row = blockIdx.x;
    float4* p = (float4*)(out + row * NN);   // 1000 floats = 250 float4
    int tid = threadIdx.x;
    float4 v = make_float4(0.f, 0.f, 0.f, 0.f);
    float s = 0.f;
    if (tid < 250) { v = p[tid]; s = (v.x + v.y) + (v.z + v.w); }
#pragma unroll
    for (int o = 16; o; o >>= 1) s += __shfl_xor_sync(0xffffffffu, s, o);
    __shared__ float ss[8];
    int w = tid >> 5, l = tid & 31;
    if (l == 0) ss[w] = s;
    __syncthreads();
    float tot = 0.f;
#pragma unroll
    for (int i = 0; i < 8; i++) tot += ss[i];
    float inv = 1.0f / tot;
    if (tid < 250) {
        v.x *= inv; v.y *= inv; v.z *= inv; v.w *= inv;
        p[tid] = v;
    }
}

extern "C" void kernel_launch(void* const* d_in, const int* in_sizes, int n_in,
                              void* d_out, int out_size) {
    const float* enc        = (const float*)d_in[0];   // [B,N,D]
    const float* q1         = (const float*)d_in[1];   // [B,P,D]
    const float* last       = (const float*)d_in[2];   // [B,P,D]
    const float* cur_dist   = (const float*)d_in[3];   // [B,P,N]
    const float* ninf_mask  = (const float*)d_in[4];   // [B,P,N]
    const float* log_scale  = (const float*)d_in[5];   // [1]
    const float* Wq_first   = (const float*)d_in[6];   // [D,D]
    const float* Wq_last    = (const float*)d_in[7];   // [D,D]
    const float* Wk         = (const float*)d_in[8];   // [D,D]
    const float* Wv         = (const float*)d_in[9];   // [D,D]
    const float* dist_alpha = (const float*)d_in[10];  // [1]
    const float* aft_alpha  = (const float*)d_in[11];  // [1]
    float* out = (float*)d_out;                        // [B,P,N]

    transpose_w<<<64, 256>>>(Wk, Wv, Wq_first, Wq_last);
    kv_mma<<<500, 256>>>(enc);
    aft_mma<<<dim3(SPLIT, 2, BB), 256>>>(cur_dist, ninf_mask, log_scale, aft_alpha);
    q_combine<<<dim3(4, 50), 256>>>(q1, last);
    score_mma<<<dim3(16, 32), 256>>>(enc, cur_dist, ninf_mask, log_scale, dist_alpha, out);
    norm_rows<<<3200, 256>>>(out);
}